// round 10
// baseline (speedup 1.0000x reference)
#include <cuda_runtime.h>
#include <math.h>
#include <stdint.h>

// Problem constants
#define BB 4
#define TT 1024
#define HH 1024
#define NHEAD 16
#define HDIM 64
#define ROWS (BB*TT)          // 4096

// ---------------- scratch (no allocs allowed) ----------------
__device__ float g_h [ROWS*HH];        // h (LN1 out), reused as h2 (LN2 out)
__device__ float g_q [ROWS*HH];        // [b][head][t][d]
__device__ float g_k [ROWS*HH];
__device__ float g_v [ROWS*HH];
__device__ float g_x1[ROWS*HH];        // x + attn out
__device__ float g_m1[ROWS*4*HH];      // gelu(h2@W1+b1)  (4096 x 4096)

// ---------------- helpers ----------------
__device__ __forceinline__ float tf32r(float x) {
    uint32_t r;
    asm("cvt.rna.tf32.f32 %0, %1;" : "=r"(r) : "f"(x));
    return __uint_as_float(r);
}

__device__ __forceinline__ void mma8(float* d, const uint32_t* a, const uint32_t* b) {
    asm volatile(
        "mma.sync.aligned.m16n8k8.row.col.f32.tf32.tf32.f32 "
        "{%0,%1,%2,%3}, {%4,%5,%6,%7}, {%8,%9}, {%0,%1,%2,%3};"
        : "+f"(d[0]), "+f"(d[1]), "+f"(d[2]), "+f"(d[3])
        : "r"(a[0]), "r"(a[1]), "r"(a[2]), "r"(a[3]), "r"(b[0]), "r"(b[1]));
}

// ---------------- LayerNorm: one block per row ----------------
__global__ __launch_bounds__(256) void ln_kernel(
    const float* __restrict__ x, const float* __restrict__ g,
    const float* __restrict__ b, float* __restrict__ out)
{
    __shared__ float red[8];
    const int row = blockIdx.x, tid = threadIdx.x;
    const float* xr = x + (size_t)row * HH;
    float4 v = *(const float4*)(xr + tid * 4);

    float s = v.x + v.y + v.z + v.w;
    #pragma unroll
    for (int o = 16; o > 0; o >>= 1) s += __shfl_xor_sync(0xffffffffu, s, o);
    if ((tid & 31) == 0) red[tid >> 5] = s;
    __syncthreads();
    float tot = red[0]+red[1]+red[2]+red[3]+red[4]+red[5]+red[6]+red[7];
    const float mu = tot * (1.0f / HH);

    float dx = v.x - mu, dy = v.y - mu, dz = v.z - mu, dw = v.w - mu;
    float ss = dx*dx + dy*dy + dz*dz + dw*dw;
    #pragma unroll
    for (int o = 16; o > 0; o >>= 1) ss += __shfl_xor_sync(0xffffffffu, ss, o);
    __syncthreads();
    if ((tid & 31) == 0) red[tid >> 5] = ss;
    __syncthreads();
    float tot2 = red[0]+red[1]+red[2]+red[3]+red[4]+red[5]+red[6]+red[7];
    const float rs = rsqrtf(tot2 * (1.0f / HH) + 1e-5f);

    float4 gv = *(const float4*)(g + tid * 4);
    float4 bv = *(const float4*)(b + tid * 4);
    float4 o4;
    o4.x = dx * rs * gv.x + bv.x;
    o4.y = dy * rs * gv.y + bv.y;
    o4.z = dz * rs * gv.z + bv.z;
    o4.w = dw * rs * gv.w + bv.w;
    *(float4*)(out + (size_t)row * HH + tid * 4) = o4;
}

// ============ tf32 mma.sync GEMM: CTA 128x128, warp 32x64, K chunks of 32 ============
// C(epilogue) = A[M,Kd] @ B[Kd,N] + bias
// Smem holds operands pre-converted to tf32 in FRAGMENT ORDER:
//  sA[(mtile*4+kstep)*128 + lane*4 + reg]   (mtile: 16 rows, kstep: k8)
//  sB[(ntile*4+kstep)*64  + lane*2 + reg]   (ntile: 8 cols)
enum { EPI_QKV = 0, EPI_GELU = 1, EPI_RES = 2 };

#define GEMM_SMEM (2 * 8192 * 4)   // 64 KB (double buffered A(16K)+B(16K))

template <int EPI>
__global__ __launch_bounds__(256) void gemm_mma(
    const float* __restrict__ A, const float* __restrict__ B,
    const float* __restrict__ bias, const float* __restrict__ resid,
    float* __restrict__ C, int N, int Kd)
{
    extern __shared__ __align__(16) float smem[];   // [2][8192]
    const int tid = threadIdx.x, lane = tid & 31, wid = tid >> 5;
    const int wm = wid & 3, wn = wid >> 2;          // 4 x 2 warp grid
    const int g = lane >> 2, c = lane & 3;
    const int bn = blockIdx.x * 128, bm = blockIdx.y * 128;
    const int KC = Kd >> 5;

    float acc[2][8][4];
    #pragma unroll
    for (int mi = 0; mi < 2; mi++)
        #pragma unroll
        for (int ni = 0; ni < 8; ni++)
            #pragma unroll
            for (int r = 0; r < 4; r++) acc[mi][ni][r] = 0.f;

    float4 va[4], vb[4];   // staging regs for next chunk

    // ---- global load of chunk kc into staging regs ----
    auto gload = [&](int kc) {
        const float* Ag = A + (size_t)bm * Kd + kc * 32;
        const float* Bg = B + (size_t)(kc * 32) * N + bn;
        #pragma unroll
        for (int i = 0; i < 4; i++) {
            int fl = tid + (i << 8);
            va[i] = *(const float4*)(Ag + (size_t)(fl >> 3) * Kd + ((fl & 7) << 2));
            vb[i] = *(const float4*)(Bg + (size_t)(fl >> 5) * N + ((fl & 31) << 2));
        }
    };
    // ---- scatter staging regs (tf32-rounded) into fragment-order smem ----
    auto sstore = [&](int buf) {
        float* sA = smem + buf * 8192;
        float* sB = sA + 4096;
        #pragma unroll
        for (int i = 0; i < 4; i++) {
            int fl = tid + (i << 8);
            // A element (r, k4*4 + j): mtile=r>>4, g=r&7, hi=(r>>3)&1
            // kstep=k4>>1, chi=k4&1, reg=hi+2*chi, lane=g*4+j
            {
                int r = fl >> 3, k4 = fl & 7;
                float* base = &sA[(((r >> 4) << 2) + (k4 >> 1)) * 128
                                  + ((r & 7) << 4) + ((r >> 3) & 1) + ((k4 & 1) << 1)];
                base[0]  = tf32r(va[i].x);
                base[4]  = tf32r(va[i].y);
                base[8]  = tf32r(va[i].z);
                base[12] = tf32r(va[i].w);
            }
            // B element (kk, n4*4 + j): ntile=n4>>1, g0=(n4&1)*4, cc=kk&3,
            // hi=(kk>>2)&1, kstep=kk>>3, lane=(g0+j)*4+cc, reg=hi
            {
                int kk = fl >> 5, n4 = fl & 31;
                float* base = &sB[(((n4 >> 1) << 2) + (kk >> 3)) * 64
                                  + ((n4 & 1) << 5) + ((kk & 3) << 1) + ((kk >> 2) & 1)];
                base[0]  = tf32r(vb[i].x);
                base[8]  = tf32r(vb[i].y);
                base[16] = tf32r(vb[i].z);
                base[24] = tf32r(vb[i].w);
            }
        }
    };
    // ---- compute one 32-K chunk from smem[buf] ----
    auto compute = [&](int buf) {
        const float* sA = smem + buf * 8192;
        const float* sB = sA + 4096;
        #pragma unroll
        for (int ks = 0; ks < 4; ks++) {
            uint32_t af[2][4];
            uint32_t bf[8][2];
            #pragma unroll
            for (int mi = 0; mi < 2; mi++) {
                int mt = wm * 2 + mi;
                *(uint4*)af[mi] =
                    *(const uint4*)&sA[((mt << 2) + ks) * 128 + (lane << 2)];
            }
            #pragma unroll
            for (int ni = 0; ni < 8; ni++) {
                int nt = wn * 8 + ni;
                *(uint2*)bf[ni] =
                    *(const uint2*)&sB[((nt << 2) + ks) * 64 + (lane << 1)];
            }
            #pragma unroll
            for (int mi = 0; mi < 2; mi++)
                #pragma unroll
                for (int ni = 0; ni < 8; ni++)
                    mma8(acc[mi][ni], af[mi], bf[ni]);
        }
    };

    gload(0);
    sstore(0);
    __syncthreads();
    int buf = 0;
    for (int kc = 0; kc < KC; kc++) {
        if (kc + 1 < KC) gload(kc + 1);
        compute(buf);
        if (kc + 1 < KC) sstore(buf ^ 1);
        __syncthreads();
        buf ^= 1;
    }

    // ---- epilogue ----
    #pragma unroll
    for (int mi = 0; mi < 2; mi++) {
        const int r0 = bm + wm * 32 + mi * 16 + g;   // second half row r0+8
        #pragma unroll
        for (int ni = 0; ni < 8; ni++) {
            const int col = bn + wn * 64 + ni * 8 + (c << 1);
            const float bx = __ldg(&bias[col]);
            const float by = __ldg(&bias[col + 1]);
            float v00 = acc[mi][ni][0] + bx, v01 = acc[mi][ni][1] + by;
            float v10 = acc[mi][ni][2] + bx, v11 = acc[mi][ni][3] + by;
            if (EPI == EPI_QKV) {
                const int head = col >> 6, d0 = col & 63;
                #pragma unroll
                for (int hh2 = 0; hh2 < 2; hh2++) {
                    const int row = r0 + hh2 * 8;
                    float* Cp = C + ((size_t)((row >> 10) * NHEAD + head)) * (TT * HDIM)
                                  + (size_t)(row & (TT - 1)) * HDIM + d0;
                    float2 o = hh2 ? make_float2(v10, v11) : make_float2(v00, v01);
                    *(float2*)Cp = o;
                }
            } else if (EPI == EPI_GELU) {
                float2 o0, o1;
                o0.x = 0.5f * v00 * (1.0f + erff(v00 * 0.70710678118654752f));
                o0.y = 0.5f * v01 * (1.0f + erff(v01 * 0.70710678118654752f));
                o1.x = 0.5f * v10 * (1.0f + erff(v10 * 0.70710678118654752f));
                o1.y = 0.5f * v11 * (1.0f + erff(v11 * 0.70710678118654752f));
                *(float2*)(C + (size_t)r0 * N + col) = o0;
                *(float2*)(C + (size_t)(r0 + 8) * N + col) = o1;
            } else {
                float2 ra = *(const float2*)(resid + (size_t)r0 * N + col);
                float2 rb = *(const float2*)(resid + (size_t)(r0 + 8) * N + col);
                float2 o0 = make_float2(v00 + ra.x, v01 + ra.y);
                float2 o1 = make_float2(v10 + rb.x, v11 + rb.y);
                *(float2*)(C + (size_t)r0 * N + col) = o0;
                *(float2*)(C + (size_t)(r0 + 8) * N + col) = o1;
            }
        }
    }
}

// ---------------- Attention with 1e-9 mask fill, fused residual ----------------
#define ST 68
#define ATTN_SMEM (size_t)((4 * 64 * ST + 3 * 64) * sizeof(float))

__global__ __launch_bounds__(256) void attn_kernel(
    const float* __restrict__ q, const float* __restrict__ k,
    const float* __restrict__ v, const float* __restrict__ x,
    float* __restrict__ x1)
{
    extern __shared__ __align__(16) char smem_raw[];
    float* sm = (float*)smem_raw;
    float* Qs = sm;
    float* Ks = Qs + 64 * ST;
    float* Vs = Ks + 64 * ST;
    float* Ss = Vs + 64 * ST;
    float* mrow = Ss + 64 * ST;
    float* lrow = mrow + 64;
    float* arow = lrow + 64;

    const int tid = threadIdx.x;
    const int tx = tid & 15, ty = tid >> 4;
    const int qt = blockIdx.x, head = blockIdx.y, b = blockIdx.z;
    const int qg0 = qt * 64;

    const float* Qg = q + (size_t)((b * NHEAD + head) * TT + qg0) * HDIM;
    const float* Kg = k + (size_t)(b * NHEAD + head) * TT * HDIM;
    const float* Vg = v + (size_t)(b * NHEAD + head) * TT * HDIM;

    for (int i = tid; i < 64 * 16; i += 256) {
        int r = i >> 4, c4 = (i & 15) << 2;
        *(float4*)&Qs[r * ST + c4] = *(const float4*)&Qg[r * 64 + c4];
    }
    if (tid < 64) { mrow[tid] = -1e30f; lrow[tid] = 0.f; }

    float acc[4][4];
    #pragma unroll
    for (int i = 0; i < 4; i++)
        #pragma unroll
        for (int j = 0; j < 4; j++) acc[i][j] = 0.f;

    for (int kt = 0; kt < 16; kt++) {
        __syncthreads();
        const float* Kt = Kg + (size_t)kt * 64 * 64;
        const float* Vt = Vg + (size_t)kt * 64 * 64;
        for (int i = tid; i < 64 * 16; i += 256) {
            int r = i >> 4, c4 = (i & 15) << 2;
            *(float4*)&Ks[r * ST + c4] = *(const float4*)&Kt[r * 64 + c4];
            *(float4*)&Vs[r * ST + c4] = *(const float4*)&Vt[r * 64 + c4];
        }
        __syncthreads();

        const int kp0 = kt * 64;
        if (kt > qt) {
            #pragma unroll
            for (int qi = 0; qi < 4; qi++)
                #pragma unroll
                for (int ki = 0; ki < 4; ki++)
                    Ss[(ty * 4 + qi) * ST + tx * 4 + ki] = 1e-9f;
        } else {
            float sacc[4][4];
            #pragma unroll
            for (int qi = 0; qi < 4; qi++)
                #pragma unroll
                for (int ki = 0; ki < 4; ki++) sacc[qi][ki] = 0.f;
            #pragma unroll 4
            for (int d = 0; d < 64; d += 4) {
                float4 qv[4], kv[4];
                #pragma unroll
                for (int qi = 0; qi < 4; qi++)
                    qv[qi] = *(const float4*)&Qs[(ty * 4 + qi) * ST + d];
                #pragma unroll
                for (int ki = 0; ki < 4; ki++)
                    kv[ki] = *(const float4*)&Ks[(tx * 4 + ki) * ST + d];
                #pragma unroll
                for (int qi = 0; qi < 4; qi++)
                    #pragma unroll
                    for (int ki = 0; ki < 4; ki++) {
                        sacc[qi][ki] += qv[qi].x * kv[ki].x;
                        sacc[qi][ki] += qv[qi].y * kv[ki].y;
                        sacc[qi][ki] += qv[qi].z * kv[ki].z;
                        sacc[qi][ki] += qv[qi].w * kv[ki].w;
                    }
            }
            #pragma unroll
            for (int qi = 0; qi < 4; qi++)
                #pragma unroll
                for (int ki = 0; ki < 4; ki++) {
                    int qq = ty * 4 + qi, kk = tx * 4 + ki;
                    float s = sacc[qi][ki] * 0.125f;
                    if (kp0 + kk > qg0 + qq) s = 1e-9f;
                    Ss[qq * ST + kk] = s;
                }
        }
        __syncthreads();

        if (tid < 64) {
            float mo = mrow[tid], mn = mo;
            const float* srow = &Ss[tid * ST];
            #pragma unroll 8
            for (int p = 0; p < 64; p++) mn = fmaxf(mn, srow[p]);
            arow[tid] = __expf(mo - mn);
            mrow[tid] = mn;
        }
        __syncthreads();

        #pragma unroll
        for (int qi = 0; qi < 4; qi++) {
            int qq = ty * 4 + qi;
            float mq = mrow[qq];
            #pragma unroll
            for (int ki = 0; ki < 4; ki++) {
                int kk = tx * 4 + ki;
                Ss[qq * ST + kk] = __expf(Ss[qq * ST + kk] - mq);
            }
        }
        __syncthreads();

        if (tid < 64) {
            float s = 0.f;
            const float* srow = &Ss[tid * ST];
            #pragma unroll 8
            for (int p = 0; p < 64; p++) s += srow[p];
            lrow[tid] = lrow[tid] * arow[tid] + s;
        }
        float al[4];
        #pragma unroll
        for (int qi = 0; qi < 4; qi++) al[qi] = arow[ty * 4 + qi];
        #pragma unroll
        for (int qi = 0; qi < 4; qi++)
            #pragma unroll
            for (int di = 0; di < 4; di++) acc[qi][di] *= al[qi];
        #pragma unroll 4
        for (int p = 0; p < 64; p += 4) {
            float4 vv0 = *(const float4*)&Vs[(p + 0) * ST + tx * 4];
            float4 vv1 = *(const float4*)&Vs[(p + 1) * ST + tx * 4];
            float4 vv2 = *(const float4*)&Vs[(p + 2) * ST + tx * 4];
            float4 vv3 = *(const float4*)&Vs[(p + 3) * ST + tx * 4];
            #pragma unroll
            for (int qi = 0; qi < 4; qi++) {
                float4 pw = *(const float4*)&Ss[(ty * 4 + qi) * ST + p];
                acc[qi][0] += pw.x * vv0.x + pw.y * vv1.x + pw.z * vv2.x + pw.w * vv3.x;
                acc[qi][1] += pw.x * vv0.y + pw.y * vv1.y + pw.z * vv2.y + pw.w * vv3.y;
                acc[qi][2] += pw.x * vv0.z + pw.y * vv1.z + pw.z * vv2.z + pw.w * vv3.z;
                acc[qi][3] += pw.x * vv0.w + pw.y * vv1.w + pw.z * vv2.w + pw.w * vv3.w;
            }
        }
    }
    __syncthreads();

    #pragma unroll
    for (int qi = 0; qi < 4; qi++) {
        int qq = ty * 4 + qi;
        float inv = 1.0f / lrow[qq];
        size_t base = ((size_t)(b * TT + qg0 + qq)) * HH + head * HDIM + tx * 4;
        #pragma unroll
        for (int di = 0; di < 4; di++)
            x1[base + di] = x[base + di] + acc[qi][di] * inv;
    }
}

// ---------------- launch ----------------
extern "C" void kernel_launch(void* const* d_in, const int* in_sizes, int n_in,
                              void* d_out, int out_size)
{
    (void)in_sizes; (void)n_in; (void)out_size;
    const float* x    = (const float*)d_in[0];
    const float* ln1g = (const float*)d_in[1];
    const float* ln1b = (const float*)d_in[2];
    const float* ln2g = (const float*)d_in[3];
    const float* ln2b = (const float*)d_in[4];
    const float* Wq   = (const float*)d_in[5];
    const float* bq   = (const float*)d_in[6];
    const float* Wk   = (const float*)d_in[7];
    const float* bk   = (const float*)d_in[8];
    const float* Wv   = (const float*)d_in[9];
    const float* bv   = (const float*)d_in[10];
    const float* W1   = (const float*)d_in[11];
    const float* b1   = (const float*)d_in[12];
    const float* W2   = (const float*)d_in[13];
    const float* b2   = (const float*)d_in[14];
    float* out = (float*)d_out;

    float *h, *q, *k, *v, *x1, *m1;
    cudaGetSymbolAddress((void**)&h,  g_h);
    cudaGetSymbolAddress((void**)&q,  g_q);
    cudaGetSymbolAddress((void**)&k,  g_k);
    cudaGetSymbolAddress((void**)&v,  g_v);
    cudaGetSymbolAddress((void**)&x1, g_x1);
    cudaGetSymbolAddress((void**)&m1, g_m1);

    cudaFuncSetAttribute(attn_kernel,
                         cudaFuncAttributeMaxDynamicSharedMemorySize, (int)ATTN_SMEM);
    cudaFuncSetAttribute(gemm_mma<EPI_QKV>,
                         cudaFuncAttributeMaxDynamicSharedMemorySize, GEMM_SMEM);
    cudaFuncSetAttribute(gemm_mma<EPI_GELU>,
                         cudaFuncAttributeMaxDynamicSharedMemorySize, GEMM_SMEM);
    cudaFuncSetAttribute(gemm_mma<EPI_RES>,
                         cudaFuncAttributeMaxDynamicSharedMemorySize, GEMM_SMEM);

    // LN1
    ln_kernel<<<ROWS, 256>>>(x, ln1g, ln1b, h);
    // QKV projections (head-permuted stores) — tf32 mma.sync tensor cores
    dim3 gqkv(HH / 128, ROWS / 128);
    gemm_mma<EPI_QKV><<<gqkv, 256, GEMM_SMEM>>>(h, Wq, bq, nullptr, q, HH, HH);
    gemm_mma<EPI_QKV><<<gqkv, 256, GEMM_SMEM>>>(h, Wk, bk, nullptr, k, HH, HH);
    gemm_mma<EPI_QKV><<<gqkv, 256, GEMM_SMEM>>>(h, Wv, bv, nullptr, v, HH, HH);
    // attention + residual
    attn_kernel<<<dim3(TT / 64, NHEAD, BB), 256, ATTN_SMEM>>>(q, k, v, x, x1);
    // LN2 (reuse h)
    ln_kernel<<<ROWS, 256>>>(x1, ln2g, ln2b, h);
    // MLP
    gemm_mma<EPI_GELU><<<dim3(4 * HH / 128, ROWS / 128), 256, GEMM_SMEM>>>(
        h, W1, b1, nullptr, m1, 4 * HH, HH);
    gemm_mma<EPI_RES><<<dim3(HH / 128, ROWS / 128), 256, GEMM_SMEM>>>(
        m1, W2, b2, x1, out, HH, 4 * HH);
}

// round 11
// speedup vs baseline: 2.5548x; 2.5548x over previous
#include <cuda_runtime.h>
#include <math.h>
#include <stdint.h>

// Problem constants
#define BB 4
#define TT 1024
#define HH 1024
#define NHEAD 16
#define HDIM 64
#define ROWS (BB*TT)          // 4096

// ---------------- scratch (no allocs allowed) ----------------
__device__ float g_hp [ROWS*HH];       // LN out, A-fragment-order (KC=32)
__device__ float g_q  [ROWS*HH];       // [b][head][t][d]
__device__ float g_k  [ROWS*HH];
__device__ float g_v  [ROWS*HH];
__device__ float g_x1 [ROWS*HH];       // x + attn out (row-major)
__device__ float g_m1 [ROWS*4*HH];     // gelu out, A-fragment-order (KC=128)
__device__ float g_wq [HH*HH];         // weights, B-fragment-order
__device__ float g_wk [HH*HH];
__device__ float g_wv [HH*HH];
__device__ float g_w1 [HH*4*HH];
__device__ float g_w2 [4*HH*HH];

// ---------------- helpers ----------------
__device__ __forceinline__ float tf32r(float x) {
    uint32_t r;
    asm("cvt.rna.tf32.f32 %0, %1;" : "=r"(r) : "f"(x));
    return __uint_as_float(r);
}
__device__ __forceinline__ uint32_t smem_u32(const void* p) {
    uint32_t a;
    asm("{ .reg .u64 t; cvta.to.shared.u64 t, %1; cvt.u32.u64 %0, t; }"
        : "=r"(a) : "l"(p));
    return a;
}
__device__ __forceinline__ void mma8(float* d, const uint32_t* a, const uint32_t* b) {
    asm volatile(
        "mma.sync.aligned.m16n8k8.row.col.f32.tf32.tf32.f32 "
        "{%0,%1,%2,%3}, {%4,%5,%6,%7}, {%8,%9}, {%0,%1,%2,%3};"
        : "+f"(d[0]), "+f"(d[1]), "+f"(d[2]), "+f"(d[3])
        : "r"(a[0]), "r"(a[1]), "r"(a[2]), "r"(a[3]), "r"(b[0]), "r"(b[1]));
}
#define CP16(dst, src) \
    asm volatile("cp.async.cg.shared.global [%0], [%1], 16;" :: "r"(dst), "l"(src))
#define CP_COMMIT() asm volatile("cp.async.commit_group;")
#define CP_WAIT1()  asm volatile("cp.async.wait_group 1;")

// ============ weight prep: W[k][n] row-major -> B-fragment-order + tf32 ============
// Output chunk (4096 floats) per (nb, kc): [nt(16)][ks(4)][lane(32)][reg(2)]
// element (k,n): reg=(k>>2)&1, lane=((n>>2)&1)*16 + (k&3) + (n&3)*4, nt=(n>>3)&15,
//               ks=(k>>3)&3
__global__ __launch_bounds__(256) void prep_w(
    const float* __restrict__ W, float* __restrict__ out, int N)
{
    __shared__ float s[32 * 132];
    const int t = threadIdx.x, kc = blockIdx.x, nb = blockIdx.y;
    const float* Wg = W + (size_t)(kc * 32) * N + nb * 128;
    #pragma unroll
    for (int i = 0; i < 4; i++) {
        int fl = t + i * 256;
        int r = fl >> 5, c4 = (fl & 31) << 2;
        float4 v = *(const float4*)(Wg + (size_t)r * N + c4);
        s[r * 132 + c4 + 0] = v.x; s[r * 132 + c4 + 1] = v.y;
        s[r * 132 + c4 + 2] = v.z; s[r * 132 + c4 + 3] = v.w;
    }
    __syncthreads();
    float* o = out + ((size_t)nb * gridDim.x + kc) * 4096 + t * 16;
    #pragma unroll
    for (int j4 = 0; j4 < 4; j4++) {
        float4 v; float* vp = (float*)&v;
        #pragma unroll
        for (int e = 0; e < 4; e++) {
            int f = t * 16 + j4 * 4 + e;
            int nt = f >> 8, ks = (f >> 6) & 3, ln = (f >> 1) & 31, rg = f & 1;
            int k3 = rg * 4 + (ln & 3);
            int nl = nt * 8 + ((ln >> 4) << 2) + ((ln >> 2) & 3);
            vp[e] = tf32r(s[(ks * 8 + k3) * 132 + nl]);
        }
        *(float4*)(o + j4 * 4) = v;
    }
}

// ---------------- LayerNorm -> A-fragment-order output (KC=32) ----------------
// A chunk (4096 floats) per (mb, kc): [mt(8)][ks(4)][lane(32)][reg(4)]
// element (m,k): mt=(m>>4)&7, hi=(m>>3)&1, g=m&7, ks=(k>>3)&3, chi=(k>>2)&1,
//               c=k&3 -> lane=g*4+c, reg=hi+2*chi
__global__ __launch_bounds__(256) void ln_kernel(
    const float* __restrict__ x, const float* __restrict__ g,
    const float* __restrict__ b, float* __restrict__ out)
{
    __shared__ float red[8];
    const int row = blockIdx.x, tid = threadIdx.x;
    const float* xr = x + (size_t)row * HH;
    float4 v = *(const float4*)(xr + tid * 4);

    float s = v.x + v.y + v.z + v.w;
    #pragma unroll
    for (int o = 16; o > 0; o >>= 1) s += __shfl_xor_sync(0xffffffffu, s, o);
    if ((tid & 31) == 0) red[tid >> 5] = s;
    __syncthreads();
    float tot = red[0]+red[1]+red[2]+red[3]+red[4]+red[5]+red[6]+red[7];
    const float mu = tot * (1.0f / HH);

    float dx = v.x - mu, dy = v.y - mu, dz = v.z - mu, dw = v.w - mu;
    float ss = dx*dx + dy*dy + dz*dz + dw*dw;
    #pragma unroll
    for (int o = 16; o > 0; o >>= 1) ss += __shfl_xor_sync(0xffffffffu, ss, o);
    __syncthreads();
    if ((tid & 31) == 0) red[tid >> 5] = ss;
    __syncthreads();
    float tot2 = red[0]+red[1]+red[2]+red[3]+red[4]+red[5]+red[6]+red[7];
    const float rs = rsqrtf(tot2 * (1.0f / HH) + 1e-5f);

    float4 gv = *(const float4*)(g + tid * 4);
    float4 bv = *(const float4*)(b + tid * 4);
    float o0 = dx * rs * gv.x + bv.x;
    float o1 = dy * rs * gv.y + bv.y;
    float o2 = dz * rs * gv.z + bv.z;
    float o3 = dw * rs * gv.w + bv.w;

    // scatter into A-fragment order (k = 4*tid .. 4*tid+3)
    const int mb = row >> 7, mt = (row >> 4) & 7, hi = (row >> 3) & 1, gg = row & 7;
    const int kc = tid >> 3, ks = (tid >> 1) & 3, chi = tid & 1;
    float* op = out + ((size_t)(mb * 32 + kc)) * 4096
              + (mt * 4 + ks) * 128 + gg * 16 + hi + 2 * chi;
    op[0]  = tf32r(o0);
    op[4]  = tf32r(o1);
    op[8]  = tf32r(o2);
    op[12] = tf32r(o3);
}

// ============ tf32 mma.sync GEMM, cp.async 3-stage, fragment-order gmem ============
enum { EPI_QKV = 0, EPI_GELU = 1, EPI_RES = 2 };

#define GEMM_SMEM (3 * 8192 * 4)   // 96 KB: 3 stages x (A 16KB + B 16KB)

template <int EPI>
__global__ __launch_bounds__(256, 2) void gemm_mma(
    const float* __restrict__ Ap, const float* __restrict__ Bp,
    const float* __restrict__ bias, const float* __restrict__ resid,
    float* __restrict__ C, int N, int Kd)
{
    extern __shared__ __align__(16) float smem[];   // [3][8192]
    const int tid = threadIdx.x, lane = tid & 31, wid = tid >> 5;
    const int wm = wid & 3, wn = wid >> 2;          // 4 x 2 warp grid
    const int gl = lane >> 2, cl = lane & 3;
    const int bn = blockIdx.x * 128, bm = blockIdx.y * 128;
    const int KC = Kd >> 5;
    const float* Ach = Ap + (size_t)blockIdx.y * KC * 4096;
    const float* Bch = Bp + (size_t)blockIdx.x * KC * 4096;
    const uint32_t sb = smem_u32(smem);

    float acc[2][8][4];
    #pragma unroll
    for (int mi = 0; mi < 2; mi++)
        #pragma unroll
        for (int ni = 0; ni < 8; ni++)
            #pragma unroll
            for (int r = 0; r < 4; r++) acc[mi][ni][r] = 0.f;

    auto issue = [&](int st, int kc) {
        if (kc < KC) {
            const float* As = Ach + (size_t)kc * 4096;
            const float* Bs = Bch + (size_t)kc * 4096;
            uint32_t da = sb + st * 32768;
            uint32_t db = da + 16384;
            #pragma unroll
            for (int i = 0; i < 4; i++) {
                int fl = (tid + i * 256) * 4;        // float index
                CP16(da + fl * 4, As + fl);
                CP16(db + fl * 4, Bs + fl);
            }
        }
        CP_COMMIT();
    };

    issue(0, 0);
    issue(1, 1);
    for (int kc = 0; kc < KC; kc++) {
        CP_WAIT1();
        __syncthreads();
        issue((kc + 2) % 3, kc + 2);    // target buffer freed by last iter's compute
        const float* sA = smem + (kc % 3) * 8192;
        const float* sB = sA + 4096;
        #pragma unroll
        for (int ks = 0; ks < 4; ks++) {
            uint32_t af[2][4];
            uint32_t bf[8][2];
            #pragma unroll
            for (int mi = 0; mi < 2; mi++) {
                int mt = wm * 2 + mi;
                *(uint4*)af[mi] =
                    *(const uint4*)&sA[((mt << 2) + ks) * 128 + (lane << 2)];
            }
            #pragma unroll
            for (int ni = 0; ni < 8; ni++) {
                int nt = wn * 8 + ni;
                *(uint2*)bf[ni] =
                    *(const uint2*)&sB[((nt << 2) + ks) * 64 + (lane << 1)];
            }
            #pragma unroll
            for (int mi = 0; mi < 2; mi++)
                #pragma unroll
                for (int ni = 0; ni < 8; ni++)
                    mma8(acc[mi][ni], af[mi], bf[ni]);
        }
    }

    // ---- epilogue ----
    #pragma unroll
    for (int mi = 0; mi < 2; mi++) {
        const int r0 = bm + wm * 32 + mi * 16 + gl;   // second half row r0+8
        #pragma unroll
        for (int ni = 0; ni < 8; ni++) {
            const int col = bn + wn * 64 + ni * 8 + (cl << 1);
            const float bx = __ldg(&bias[col]);
            const float by = __ldg(&bias[col + 1]);
            float v00 = acc[mi][ni][0] + bx, v01 = acc[mi][ni][1] + by;
            float v10 = acc[mi][ni][2] + bx, v11 = acc[mi][ni][3] + by;
            if (EPI == EPI_QKV) {
                const int head = col >> 6, d0 = col & 63;
                #pragma unroll
                for (int hh2 = 0; hh2 < 2; hh2++) {
                    const int row = r0 + hh2 * 8;
                    float* Cp = C + ((size_t)((row >> 10) * NHEAD + head)) * (TT * HDIM)
                                  + (size_t)(row & (TT - 1)) * HDIM + d0;
                    float2 o = hh2 ? make_float2(v10, v11) : make_float2(v00, v01);
                    *(float2*)Cp = o;
                }
            } else if (EPI == EPI_GELU) {
                // exact gelu, then store m1 in A-fragment order for the W2 GEMM
                // (consumer KC = 128). (r0,col)&(r0+8,col) are adjacent regs;
                // col+1 is +4 floats.
                float t00 = 0.5f * v00 * (1.0f + erff(v00 * 0.70710678118654752f));
                float t01 = 0.5f * v01 * (1.0f + erff(v01 * 0.70710678118654752f));
                float t10 = 0.5f * v10 * (1.0f + erff(v10 * 0.70710678118654752f));
                float t11 = 0.5f * v11 * (1.0f + erff(v11 * 0.70710678118654752f));
                size_t idx = ((size_t)((r0 >> 7) * 128 + (col >> 5))) * 4096
                           + ((((r0 >> 4) & 7) << 2) + ((col >> 3) & 3)) * 128
                           + (((r0 & 7) << 2) + (col & 3)) * 4
                           + ((col >> 2) & 1) * 2;
                *(float2*)(C + idx)     = make_float2(tf32r(t00), tf32r(t10));
                *(float2*)(C + idx + 4) = make_float2(tf32r(t01), tf32r(t11));
            } else {
                float2 ra = *(const float2*)(resid + (size_t)r0 * N + col);
                float2 rb = *(const float2*)(resid + (size_t)(r0 + 8) * N + col);
                *(float2*)(C + (size_t)r0 * N + col) =
                    make_float2(v00 + ra.x, v01 + ra.y);
                *(float2*)(C + (size_t)(r0 + 8) * N + col) =
                    make_float2(v10 + rb.x, v11 + rb.y);
            }
        }
    }
}

// ---------------- Attention with 1e-9 mask fill, fused residual ----------------
#define ST 68
#define ATTN_SMEM (size_t)((4 * 64 * ST + 3 * 64) * sizeof(float))

__global__ __launch_bounds__(256) void attn_kernel(
    const float* __restrict__ q, const float* __restrict__ k,
    const float* __restrict__ v, const float* __restrict__ x,
    float* __restrict__ x1)
{
    extern __shared__ __align__(16) char smem_raw[];
    float* sm = (float*)smem_raw;
    float* Qs = sm;
    float* Ks = Qs + 64 * ST;
    float* Vs = Ks + 64 * ST;
    float* Ss = Vs + 64 * ST;
    float* mrow = Ss + 64 * ST;
    float* lrow = mrow + 64;
    float* arow = lrow + 64;

    const int tid = threadIdx.x;
    const int tx = tid & 15, ty = tid >> 4;
    const int qt = blockIdx.x, head = blockIdx.y, b = blockIdx.z;
    const int qg0 = qt * 64;

    const float* Qg = q + (size_t)((b * NHEAD + head) * TT + qg0) * HDIM;
    const float* Kg = k + (size_t)(b * NHEAD + head) * TT * HDIM;
    const float* Vg = v + (size_t)(b * NHEAD + head) * TT * HDIM;

    for (int i = tid; i < 64 * 16; i += 256) {
        int r = i >> 4, c4 = (i & 15) << 2;
        *(float4*)&Qs[r * ST + c4] = *(const float4*)&Qg[r * 64 + c4];
    }
    if (tid < 64) { mrow[tid] = -1e30f; lrow[tid] = 0.f; }

    float acc[4][4];
    #pragma unroll
    for (int i = 0; i < 4; i++)
        #pragma unroll
        for (int j = 0; j < 4; j++) acc[i][j] = 0.f;

    for (int kt = 0; kt < 16; kt++) {
        __syncthreads();
        const float* Kt = Kg + (size_t)kt * 64 * 64;
        const float* Vt = Vg + (size_t)kt * 64 * 64;
        for (int i = tid; i < 64 * 16; i += 256) {
            int r = i >> 4, c4 = (i & 15) << 2;
            *(float4*)&Ks[r * ST + c4] = *(const float4*)&Kt[r * 64 + c4];
            *(float4*)&Vs[r * ST + c4] = *(const float4*)&Vt[r * 64 + c4];
        }
        __syncthreads();

        const int kp0 = kt * 64;
        if (kt > qt) {
            #pragma unroll
            for (int qi = 0; qi < 4; qi++)
                #pragma unroll
                for (int ki = 0; ki < 4; ki++)
                    Ss[(ty * 4 + qi) * ST + tx * 4 + ki] = 1e-9f;
        } else {
            float sacc[4][4];
            #pragma unroll
            for (int qi = 0; qi < 4; qi++)
                #pragma unroll
                for (int ki = 0; ki < 4; ki++) sacc[qi][ki] = 0.f;
            #pragma unroll 4
            for (int d = 0; d < 64; d += 4) {
                float4 qv[4], kv[4];
                #pragma unroll
                for (int qi = 0; qi < 4; qi++)
                    qv[qi] = *(const float4*)&Qs[(ty * 4 + qi) * ST + d];
                #pragma unroll
                for (int ki = 0; ki < 4; ki++)
                    kv[ki] = *(const float4*)&Ks[(tx * 4 + ki) * ST + d];
                #pragma unroll
                for (int qi = 0; qi < 4; qi++)
                    #pragma unroll
                    for (int ki = 0; ki < 4; ki++) {
                        sacc[qi][ki] += qv[qi].x * kv[ki].x;
                        sacc[qi][ki] += qv[qi].y * kv[ki].y;
                        sacc[qi][ki] += qv[qi].z * kv[ki].z;
                        sacc[qi][ki] += qv[qi].w * kv[ki].w;
                    }
            }
            #pragma unroll
            for (int qi = 0; qi < 4; qi++)
                #pragma unroll
                for (int ki = 0; ki < 4; ki++) {
                    int qq = ty * 4 + qi, kk = tx * 4 + ki;
                    float s = sacc[qi][ki] * 0.125f;
                    if (kp0 + kk > qg0 + qq) s = 1e-9f;
                    Ss[qq * ST + kk] = s;
                }
        }
        __syncthreads();

        if (tid < 64) {
            float mo = mrow[tid], mn = mo;
            const float* srow = &Ss[tid * ST];
            #pragma unroll 8
            for (int p = 0; p < 64; p++) mn = fmaxf(mn, srow[p]);
            arow[tid] = __expf(mo - mn);
            mrow[tid] = mn;
        }
        __syncthreads();

        #pragma unroll
        for (int qi = 0; qi < 4; qi++) {
            int qq = ty * 4 + qi;
            float mq = mrow[qq];
            #pragma unroll
            for (int ki = 0; ki < 4; ki++) {
                int kk = tx * 4 + ki;
                Ss[qq * ST + kk] = __expf(Ss[qq * ST + kk] - mq);
            }
        }
        __syncthreads();

        if (tid < 64) {
            float s = 0.f;
            const float* srow = &Ss[tid * ST];
            #pragma unroll 8
            for (int p = 0; p < 64; p++) s += srow[p];
            lrow[tid] = lrow[tid] * arow[tid] + s;
        }
        float al[4];
        #pragma unroll
        for (int qi = 0; qi < 4; qi++) al[qi] = arow[ty * 4 + qi];
        #pragma unroll
        for (int qi = 0; qi < 4; qi++)
            #pragma unroll
            for (int di = 0; di < 4; di++) acc[qi][di] *= al[qi];
        #pragma unroll 4
        for (int p = 0; p < 64; p += 4) {
            float4 vv0 = *(const float4*)&Vs[(p + 0) * ST + tx * 4];
            float4 vv1 = *(const float4*)&Vs[(p + 1) * ST + tx * 4];
            float4 vv2 = *(const float4*)&Vs[(p + 2) * ST + tx * 4];
            float4 vv3 = *(const float4*)&Vs[(p + 3) * ST + tx * 4];
            #pragma unroll
            for (int qi = 0; qi < 4; qi++) {
                float4 pw = *(const float4*)&Ss[(ty * 4 + qi) * ST + p];
                acc[qi][0] += pw.x * vv0.x + pw.y * vv1.x + pw.z * vv2.x + pw.w * vv3.x;
                acc[qi][1] += pw.x * vv0.y + pw.y * vv1.y + pw.z * vv2.y + pw.w * vv3.y;
                acc[qi][2] += pw.x * vv0.z + pw.y * vv1.z + pw.z * vv2.z + pw.w * vv3.z;
                acc[qi][3] += pw.x * vv0.w + pw.y * vv1.w + pw.z * vv2.w + pw.w * vv3.w;
            }
        }
    }
    __syncthreads();

    #pragma unroll
    for (int qi = 0; qi < 4; qi++) {
        int qq = ty * 4 + qi;
        float inv = 1.0f / lrow[qq];
        size_t base = ((size_t)(b * TT + qg0 + qq)) * HH + head * HDIM + tx * 4;
        #pragma unroll
        for (int di = 0; di < 4; di++)
            x1[base + di] = x[base + di] + acc[qi][di] * inv;
    }
}

// ---------------- launch ----------------
extern "C" void kernel_launch(void* const* d_in, const int* in_sizes, int n_in,
                              void* d_out, int out_size)
{
    (void)in_sizes; (void)n_in; (void)out_size;
    const float* x    = (const float*)d_in[0];
    const float* ln1g = (const float*)d_in[1];
    const float* ln1b = (const float*)d_in[2];
    const float* ln2g = (const float*)d_in[3];
    const float* ln2b = (const float*)d_in[4];
    const float* Wq   = (const float*)d_in[5];
    const float* bq   = (const float*)d_in[6];
    const float* Wk   = (const float*)d_in[7];
    const float* bk   = (const float*)d_in[8];
    const float* Wv   = (const float*)d_in[9];
    const float* bv   = (const float*)d_in[10];
    const float* W1   = (const float*)d_in[11];
    const float* b1   = (const float*)d_in[12];
    const float* W2   = (const float*)d_in[13];
    const float* b2   = (const float*)d_in[14];
    float* out = (float*)d_out;

    float *hp, *q, *k, *v, *x1, *m1, *wq, *wk, *wv, *w1, *w2;
    cudaGetSymbolAddress((void**)&hp, g_hp);
    cudaGetSymbolAddress((void**)&q,  g_q);
    cudaGetSymbolAddress((void**)&k,  g_k);
    cudaGetSymbolAddress((void**)&v,  g_v);
    cudaGetSymbolAddress((void**)&x1, g_x1);
    cudaGetSymbolAddress((void**)&m1, g_m1);
    cudaGetSymbolAddress((void**)&wq, g_wq);
    cudaGetSymbolAddress((void**)&wk, g_wk);
    cudaGetSymbolAddress((void**)&wv, g_wv);
    cudaGetSymbolAddress((void**)&w1, g_w1);
    cudaGetSymbolAddress((void**)&w2, g_w2);

    cudaFuncSetAttribute(attn_kernel,
                         cudaFuncAttributeMaxDynamicSharedMemorySize, (int)ATTN_SMEM);
    cudaFuncSetAttribute(gemm_mma<EPI_QKV>,
                         cudaFuncAttributeMaxDynamicSharedMemorySize, GEMM_SMEM);
    cudaFuncSetAttribute(gemm_mma<EPI_GELU>,
                         cudaFuncAttributeMaxDynamicSharedMemorySize, GEMM_SMEM);
    cudaFuncSetAttribute(gemm_mma<EPI_RES>,
                         cudaFuncAttributeMaxDynamicSharedMemorySize, GEMM_SMEM);

    // weight prep: permute + tf32-round into B-fragment order
    prep_w<<<dim3(32, 8),  256>>>(Wq, wq, HH);
    prep_w<<<dim3(32, 8),  256>>>(Wk, wk, HH);
    prep_w<<<dim3(32, 8),  256>>>(Wv, wv, HH);
    prep_w<<<dim3(32, 32), 256>>>(W1, w1, 4 * HH);
    prep_w<<<dim3(128, 8), 256>>>(W2, w2, HH);

    // LN1 -> hp (A-fragment order)
    ln_kernel<<<ROWS, 256>>>(x, ln1g, ln1b, hp);
    // QKV projections (head-permuted stores)
    dim3 gqkv(HH / 128, ROWS / 128);
    gemm_mma<EPI_QKV><<<gqkv, 256, GEMM_SMEM>>>(hp, wq, bq, nullptr, q, HH, HH);
    gemm_mma<EPI_QKV><<<gqkv, 256, GEMM_SMEM>>>(hp, wk, bk, nullptr, k, HH, HH);
    gemm_mma<EPI_QKV><<<gqkv, 256, GEMM_SMEM>>>(hp, wv, bv, nullptr, v, HH, HH);
    // attention + residual
    attn_kernel<<<dim3(TT / 64, NHEAD, BB), 256, ATTN_SMEM>>>(q, k, v, x, x1);
    // LN2 -> hp (A-fragment order)
    ln_kernel<<<ROWS, 256>>>(x1, ln2g, ln2b, hp);
    // MLP: W1 gemm writes m1 in A-fragment order; W2 gemm reads it back
    gemm_mma<EPI_GELU><<<dim3(4 * HH / 128, ROWS / 128), 256, GEMM_SMEM>>>(
        hp, w1, b1, nullptr, m1, 4 * HH, HH);
    gemm_mma<EPI_RES><<<dim3(HH / 128, ROWS / 128), 256, GEMM_SMEM>>>(
        m1, w2, b2, x1, out, HH, 4 * HH);
}

// round 12
// speedup vs baseline: 2.7816x; 1.0888x over previous
#include <cuda_runtime.h>
#include <math.h>
#include <stdint.h>

// Problem constants
#define BB 4
#define TT 1024
#define HH 1024
#define NHEAD 16
#define HDIM 64
#define ROWS (BB*TT)          // 4096

// ---------------- scratch (no allocs allowed) ----------------
__device__ float g_hp [ROWS*HH];       // LN out, A-fragment-order (KC=32)
__device__ float g_q  [ROWS*HH];       // [b][head][t][d]
__device__ float g_k  [ROWS*HH];
__device__ float g_v  [ROWS*HH];
__device__ float g_x1 [ROWS*HH];       // x + attn out (row-major)
__device__ float g_m1 [ROWS*4*HH];     // gelu out, A-fragment-order (KC=128)
__device__ float g_wq [HH*HH];         // weights, B-fragment-order
__device__ float g_wk [HH*HH];
__device__ float g_wv [HH*HH];
__device__ float g_w1 [HH*4*HH];
__device__ float g_w2 [4*HH*HH];

// ---------------- helpers ----------------
__device__ __forceinline__ float tf32r(float x) {
    uint32_t r;
    asm("cvt.rna.tf32.f32 %0, %1;" : "=r"(r) : "f"(x));
    return __uint_as_float(r);
}
__device__ __forceinline__ uint32_t smem_u32(const void* p) {
    uint32_t a;
    asm("{ .reg .u64 t; cvta.to.shared.u64 t, %1; cvt.u32.u64 %0, t; }"
        : "=r"(a) : "l"(p));
    return a;
}
__device__ __forceinline__ void mma8(float* d, const uint32_t* a, const uint32_t* b) {
    asm volatile(
        "mma.sync.aligned.m16n8k8.row.col.f32.tf32.tf32.f32 "
        "{%0,%1,%2,%3}, {%4,%5,%6,%7}, {%8,%9}, {%0,%1,%2,%3};"
        : "+f"(d[0]), "+f"(d[1]), "+f"(d[2]), "+f"(d[3])
        : "r"(a[0]), "r"(a[1]), "r"(a[2]), "r"(a[3]), "r"(b[0]), "r"(b[1]));
}
#define CP16(dst, src) \
    asm volatile("cp.async.cg.shared.global [%0], [%1], 16;" :: "r"(dst), "l"(src))
#define CP_COMMIT() asm volatile("cp.async.commit_group;")
#define CP_WAIT1()  asm volatile("cp.async.wait_group 1;")

// ============ weight prep: W[k][n] row-major -> B-fragment-order + tf32 ============
// Output chunk (4096 floats) per (nb, kc): [nt(16)][ks(4)][lane(32)][reg(2)]
__global__ __launch_bounds__(256) void prep_w(
    const float* __restrict__ W, float* __restrict__ out, int N)
{
    __shared__ float s[32 * 132];
    const int t = threadIdx.x, kc = blockIdx.x, nb = blockIdx.y;
    const float* Wg = W + (size_t)(kc * 32) * N + nb * 128;
    #pragma unroll
    for (int i = 0; i < 4; i++) {
        int fl = t + i * 256;
        int r = fl >> 5, c4 = (fl & 31) << 2;
        float4 v = *(const float4*)(Wg + (size_t)r * N + c4);
        s[r * 132 + c4 + 0] = v.x; s[r * 132 + c4 + 1] = v.y;
        s[r * 132 + c4 + 2] = v.z; s[r * 132 + c4 + 3] = v.w;
    }
    __syncthreads();
    float* o = out + ((size_t)nb * gridDim.x + kc) * 4096 + t * 16;
    #pragma unroll
    for (int j4 = 0; j4 < 4; j4++) {
        float4 v; float* vp = (float*)&v;
        #pragma unroll
        for (int e = 0; e < 4; e++) {
            int f = t * 16 + j4 * 4 + e;
            int nt = f >> 8, ks = (f >> 6) & 3, ln = (f >> 1) & 31, rg = f & 1;
            int k3 = rg * 4 + (ln & 3);
            int nl = nt * 8 + ((ln >> 4) << 2) + ((ln >> 2) & 3);
            vp[e] = tf32r(s[(ks * 8 + k3) * 132 + nl]);
        }
        *(float4*)(o + j4 * 4) = v;
    }
}

// ---------------- LayerNorm -> A-fragment-order output (KC=32) ----------------
__global__ __launch_bounds__(256) void ln_kernel(
    const float* __restrict__ x, const float* __restrict__ g,
    const float* __restrict__ b, float* __restrict__ out)
{
    __shared__ float red[8];
    const int row = blockIdx.x, tid = threadIdx.x;
    const float* xr = x + (size_t)row * HH;
    float4 v = *(const float4*)(xr + tid * 4);

    float s = v.x + v.y + v.z + v.w;
    #pragma unroll
    for (int o = 16; o > 0; o >>= 1) s += __shfl_xor_sync(0xffffffffu, s, o);
    if ((tid & 31) == 0) red[tid >> 5] = s;
    __syncthreads();
    float tot = red[0]+red[1]+red[2]+red[3]+red[4]+red[5]+red[6]+red[7];
    const float mu = tot * (1.0f / HH);

    float dx = v.x - mu, dy = v.y - mu, dz = v.z - mu, dw = v.w - mu;
    float ss = dx*dx + dy*dy + dz*dz + dw*dw;
    #pragma unroll
    for (int o = 16; o > 0; o >>= 1) ss += __shfl_xor_sync(0xffffffffu, ss, o);
    __syncthreads();
    if ((tid & 31) == 0) red[tid >> 5] = ss;
    __syncthreads();
    float tot2 = red[0]+red[1]+red[2]+red[3]+red[4]+red[5]+red[6]+red[7];
    const float rs = rsqrtf(tot2 * (1.0f / HH) + 1e-5f);

    float4 gv = *(const float4*)(g + tid * 4);
    float4 bv = *(const float4*)(b + tid * 4);
    float o0 = dx * rs * gv.x + bv.x;
    float o1 = dy * rs * gv.y + bv.y;
    float o2 = dz * rs * gv.z + bv.z;
    float o3 = dw * rs * gv.w + bv.w;

    // scatter into A-fragment order (k = 4*tid .. 4*tid+3)
    const int mb = row >> 7, mt = (row >> 4) & 7, hi = (row >> 3) & 1, gg = row & 7;
    const int kc = tid >> 3, ks = (tid >> 1) & 3, chi = tid & 1;
    float* op = out + ((size_t)(mb * 32 + kc)) * 4096
              + (mt * 4 + ks) * 128 + gg * 16 + hi + 2 * chi;
    op[0]  = tf32r(o0);
    op[4]  = tf32r(o1);
    op[8]  = tf32r(o2);
    op[12] = tf32r(o3);
}

// ============ tf32 mma.sync GEMM, cp.async 3-stage, fragment-order gmem ============
enum { EPI_QKV = 0, EPI_GELU = 1, EPI_RES = 2 };

#define GEMM_SMEM (3 * 8192 * 4)   // 96 KB: 3 stages x (A 16KB + B 16KB)

template <int EPI>
__global__ __launch_bounds__(256, 2) void gemm_mma(
    const float* __restrict__ Ap, const float* __restrict__ Bp,
    const float* __restrict__ bias, const float* __restrict__ resid,
    float* __restrict__ C, int N, int Kd)
{
    extern __shared__ __align__(16) float smem[];   // [3][8192]
    const int tid = threadIdx.x, lane = tid & 31, wid = tid >> 5;
    const int wm = wid & 3, wn = wid >> 2;          // 4 x 2 warp grid
    const int gl = lane >> 2, cl = lane & 3;
    const int bn = blockIdx.x * 128, bm = blockIdx.y * 128;
    const int KC = Kd >> 5;
    const float* Ach = Ap + (size_t)blockIdx.y * KC * 4096;
    const float* Bch = Bp + (size_t)blockIdx.x * KC * 4096;
    const uint32_t sb = smem_u32(smem);

    float acc[2][8][4];
    #pragma unroll
    for (int mi = 0; mi < 2; mi++)
        #pragma unroll
        for (int ni = 0; ni < 8; ni++)
            #pragma unroll
            for (int r = 0; r < 4; r++) acc[mi][ni][r] = 0.f;

    auto issue = [&](int st, int kc) {
        if (kc < KC) {
            const float* As = Ach + (size_t)kc * 4096;
            const float* Bs = Bch + (size_t)kc * 4096;
            uint32_t da = sb + st * 32768;
            uint32_t db = da + 16384;
            #pragma unroll
            for (int i = 0; i < 4; i++) {
                int fl = (tid + i * 256) * 4;        // float index
                CP16(da + fl * 4, As + fl);
                CP16(db + fl * 4, Bs + fl);
            }
        }
        CP_COMMIT();
    };

    issue(0, 0);
    issue(1, 1);
    for (int kc = 0; kc < KC; kc++) {
        CP_WAIT1();
        __syncthreads();
        issue((kc + 2) % 3, kc + 2);
        const float* sA = smem + (kc % 3) * 8192;
        const float* sB = sA + 4096;
        #pragma unroll
        for (int ks = 0; ks < 4; ks++) {
            uint32_t af[2][4];
            uint32_t bf[8][2];
            #pragma unroll
            for (int mi = 0; mi < 2; mi++) {
                int mt = wm * 2 + mi;
                *(uint4*)af[mi] =
                    *(const uint4*)&sA[((mt << 2) + ks) * 128 + (lane << 2)];
            }
            #pragma unroll
            for (int ni = 0; ni < 8; ni++) {
                int nt = wn * 8 + ni;
                *(uint2*)bf[ni] =
                    *(const uint2*)&sB[((nt << 2) + ks) * 64 + (lane << 1)];
            }
            #pragma unroll
            for (int mi = 0; mi < 2; mi++)
                #pragma unroll
                for (int ni = 0; ni < 8; ni++)
                    mma8(acc[mi][ni], af[mi], bf[ni]);
        }
    }

    // ---- epilogue ----
    #pragma unroll
    for (int mi = 0; mi < 2; mi++) {
        const int r0 = bm + wm * 32 + mi * 16 + gl;   // second half row r0+8
        #pragma unroll
        for (int ni = 0; ni < 8; ni++) {
            const int col = bn + wn * 64 + ni * 8 + (cl << 1);
            const float bx = __ldg(&bias[col]);
            const float by = __ldg(&bias[col + 1]);
            float v00 = acc[mi][ni][0] + bx, v01 = acc[mi][ni][1] + by;
            float v10 = acc[mi][ni][2] + bx, v11 = acc[mi][ni][3] + by;
            if (EPI == EPI_QKV) {
                const int head = col >> 6, d0 = col & 63;
                #pragma unroll
                for (int hh2 = 0; hh2 < 2; hh2++) {
                    const int row = r0 + hh2 * 8;
                    float* Cp = C + ((size_t)((row >> 10) * NHEAD + head)) * (TT * HDIM)
                                  + (size_t)(row & (TT - 1)) * HDIM + d0;
                    float2 o = hh2 ? make_float2(v10, v11) : make_float2(v00, v01);
                    *(float2*)Cp = o;
                }
            } else if (EPI == EPI_GELU) {
                float t00 = 0.5f * v00 * (1.0f + erff(v00 * 0.70710678118654752f));
                float t01 = 0.5f * v01 * (1.0f + erff(v01 * 0.70710678118654752f));
                float t10 = 0.5f * v10 * (1.0f + erff(v10 * 0.70710678118654752f));
                float t11 = 0.5f * v11 * (1.0f + erff(v11 * 0.70710678118654752f));
                size_t idx = ((size_t)((r0 >> 7) * 128 + (col >> 5))) * 4096
                           + ((((r0 >> 4) & 7) << 2) + ((col >> 3) & 3)) * 128
                           + (((r0 & 7) << 2) + (col & 3)) * 4
                           + ((col >> 2) & 1) * 2;
                *(float2*)(C + idx)     = make_float2(tf32r(t00), tf32r(t10));
                *(float2*)(C + idx + 4) = make_float2(tf32r(t01), tf32r(t11));
            } else {
                float2 ra = *(const float2*)(resid + (size_t)r0 * N + col);
                float2 rb = *(const float2*)(resid + (size_t)(r0 + 8) * N + col);
                *(float2*)(C + (size_t)r0 * N + col) =
                    make_float2(v00 + ra.x, v01 + ra.y);
                *(float2*)(C + (size_t)(r0 + 8) * N + col) =
                    make_float2(v10 + rb.x, v11 + rb.y);
            }
        }
    }
}

// ---------------- Attention with 1e-9 mask fill, fused residual ----------------
// Flash loop over kt <= qt only; fully-masked tiles folded in analytically:
// every masked score is the constant 1e-9, so their softmax contribution is
// Nmask*exp(1e-9-m) to l and exp(1e-9-m)*colsum(V_masked) to acc (row-indep).
#define ST 68
#define ATTN_SMEM (size_t)((4 * 64 * ST + 3 * 64) * sizeof(float))

__global__ __launch_bounds__(256) void attn_kernel(
    const float* __restrict__ q, const float* __restrict__ k,
    const float* __restrict__ v, const float* __restrict__ x,
    float* __restrict__ x1)
{
    extern __shared__ __align__(16) char smem_raw[];
    float* sm = (float*)smem_raw;
    float* Qs = sm;
    float* Ks = Qs + 64 * ST;
    float* Vs = Ks + 64 * ST;
    float* Ss = Vs + 64 * ST;       // scores / probs; reused as vpart after loop
    float* mrow = Ss + 64 * ST;     // running max; reused as e after loop
    float* lrow = mrow + 64;
    float* arow = lrow + 64;

    const int tid = threadIdx.x;
    const int tx = tid & 15, ty = tid >> 4;
    const int qt = blockIdx.x, head = blockIdx.y, b = blockIdx.z;
    const int qg0 = qt * 64;

    const float* Qg = q + (size_t)((b * NHEAD + head) * TT + qg0) * HDIM;
    const float* Kg = k + (size_t)(b * NHEAD + head) * TT * HDIM;
    const float* Vg = v + (size_t)(b * NHEAD + head) * TT * HDIM;

    for (int i = tid; i < 64 * 16; i += 256) {
        int r = i >> 4, c4 = (i & 15) << 2;
        *(float4*)&Qs[r * ST + c4] = *(const float4*)&Qg[r * 64 + c4];
    }
    if (tid < 64) { mrow[tid] = -1e30f; lrow[tid] = 0.f; }

    float acc[4][4];
    #pragma unroll
    for (int i = 0; i < 4; i++)
        #pragma unroll
        for (int j = 0; j < 4; j++) acc[i][j] = 0.f;

    for (int kt = 0; kt <= qt; kt++) {
        __syncthreads();
        const float* Kt = Kg + (size_t)kt * 64 * 64;
        const float* Vt = Vg + (size_t)kt * 64 * 64;
        for (int i = tid; i < 64 * 16; i += 256) {
            int r = i >> 4, c4 = (i & 15) << 2;
            *(float4*)&Ks[r * ST + c4] = *(const float4*)&Kt[r * 64 + c4];
            *(float4*)&Vs[r * ST + c4] = *(const float4*)&Vt[r * 64 + c4];
        }
        __syncthreads();

        const int kp0 = kt * 64;
        {
            float sacc[4][4];
            #pragma unroll
            for (int qi = 0; qi < 4; qi++)
                #pragma unroll
                for (int ki = 0; ki < 4; ki++) sacc[qi][ki] = 0.f;
            #pragma unroll 4
            for (int d = 0; d < 64; d += 4) {
                float4 qv[4], kv[4];
                #pragma unroll
                for (int qi = 0; qi < 4; qi++)
                    qv[qi] = *(const float4*)&Qs[(ty * 4 + qi) * ST + d];
                #pragma unroll
                for (int ki = 0; ki < 4; ki++)
                    kv[ki] = *(const float4*)&Ks[(tx * 4 + ki) * ST + d];
                #pragma unroll
                for (int qi = 0; qi < 4; qi++)
                    #pragma unroll
                    for (int ki = 0; ki < 4; ki++) {
                        sacc[qi][ki] += qv[qi].x * kv[ki].x;
                        sacc[qi][ki] += qv[qi].y * kv[ki].y;
                        sacc[qi][ki] += qv[qi].z * kv[ki].z;
                        sacc[qi][ki] += qv[qi].w * kv[ki].w;
                    }
            }
            #pragma unroll
            for (int qi = 0; qi < 4; qi++)
                #pragma unroll
                for (int ki = 0; ki < 4; ki++) {
                    int qq = ty * 4 + qi, kk = tx * 4 + ki;
                    float s = sacc[qi][ki] * 0.125f;
                    if (kp0 + kk > qg0 + qq) s = 1e-9f;   // diagonal-tile mask FILL
                    Ss[qq * ST + kk] = s;
                }
        }
        __syncthreads();

        if (tid < 64) {
            float mo = mrow[tid], mn = mo;
            const float* srow = &Ss[tid * ST];
            #pragma unroll 8
            for (int p = 0; p < 64; p++) mn = fmaxf(mn, srow[p]);
            arow[tid] = __expf(mo - mn);
            mrow[tid] = mn;
        }
        __syncthreads();

        #pragma unroll
        for (int qi = 0; qi < 4; qi++) {
            int qq = ty * 4 + qi;
            float mq = mrow[qq];
            #pragma unroll
            for (int ki = 0; ki < 4; ki++) {
                int kk = tx * 4 + ki;
                Ss[qq * ST + kk] = __expf(Ss[qq * ST + kk] - mq);
            }
        }
        __syncthreads();

        if (tid < 64) {
            float s = 0.f;
            const float* srow = &Ss[tid * ST];
            #pragma unroll 8
            for (int p = 0; p < 64; p++) s += srow[p];
            lrow[tid] = lrow[tid] * arow[tid] + s;
        }
        float al[4];
        #pragma unroll
        for (int qi = 0; qi < 4; qi++) al[qi] = arow[ty * 4 + qi];
        #pragma unroll
        for (int qi = 0; qi < 4; qi++)
            #pragma unroll
            for (int di = 0; di < 4; di++) acc[qi][di] *= al[qi];
        #pragma unroll 4
        for (int p = 0; p < 64; p += 4) {
            float4 vv0 = *(const float4*)&Vs[(p + 0) * ST + tx * 4];
            float4 vv1 = *(const float4*)&Vs[(p + 1) * ST + tx * 4];
            float4 vv2 = *(const float4*)&Vs[(p + 2) * ST + tx * 4];
            float4 vv3 = *(const float4*)&Vs[(p + 3) * ST + tx * 4];
            #pragma unroll
            for (int qi = 0; qi < 4; qi++) {
                float4 pw = *(const float4*)&Ss[(ty * 4 + qi) * ST + p];
                acc[qi][0] += pw.x * vv0.x + pw.y * vv1.x + pw.z * vv2.x + pw.w * vv3.x;
                acc[qi][1] += pw.x * vv0.y + pw.y * vv1.y + pw.z * vv2.y + pw.w * vv3.y;
                acc[qi][2] += pw.x * vv0.z + pw.y * vv1.z + pw.z * vv2.z + pw.w * vv3.z;
                acc[qi][3] += pw.x * vv0.w + pw.y * vv1.w + pw.z * vv2.w + pw.w * vv3.w;
            }
        }
    }
    __syncthreads();   // mainloop done; Ss free for reuse

    // ---- virtual masked tile: rows [(qt+1)*64, 1024) all have score 1e-9 ----
    if (qt < 15) {
        const int mstart = (qt + 1) * 64;
        const float nmask = (float)(TT - mstart);
        // column sums of masked V region (coalesced; 4 partials per column)
        float* vpart = Ss;                   // reuse: [4][64]
        {
            float ps = 0.f;
            const int col = tid & 63, seg = tid >> 6;
            for (int r = mstart + seg; r < TT; r += 4)
                ps += Vg[(size_t)r * 64 + col];
            vpart[seg * 64 + col] = ps;
        }
        if (tid < 64) {
            float mo = mrow[tid], mn = fmaxf(mo, 1e-9f);
            float a = __expf(mo - mn);
            float e = __expf(1e-9f - mn);
            arow[tid] = a;
            mrow[tid] = e;                   // reuse mrow to carry e
            lrow[tid] = lrow[tid] * a + nmask * e;
        }
        __syncthreads();
        float al[4], el[4];
        #pragma unroll
        for (int qi = 0; qi < 4; qi++) {
            al[qi] = arow[ty * 4 + qi];
            el[qi] = mrow[ty * 4 + qi];
        }
        float vs[4];
        #pragma unroll
        for (int di = 0; di < 4; di++) {
            int col = tx * 4 + di;
            vs[di] = vpart[col] + vpart[64 + col] + vpart[128 + col] + vpart[192 + col];
        }
        #pragma unroll
        for (int qi = 0; qi < 4; qi++)
            #pragma unroll
            for (int di = 0; di < 4; di++)
                acc[qi][di] = acc[qi][di] * al[qi] + el[qi] * vs[di];
        __syncthreads();
    }

    // epilogue: x1 = x + y   (y back to [b][t][H] layout)
    #pragma unroll
    for (int qi = 0; qi < 4; qi++) {
        int qq = ty * 4 + qi;
        float inv = 1.0f / lrow[qq];
        size_t base = ((size_t)(b * TT + qg0 + qq)) * HH + head * HDIM + tx * 4;
        #pragma unroll
        for (int di = 0; di < 4; di++)
            x1[base + di] = x[base + di] + acc[qi][di] * inv;
    }
}

// ---------------- launch ----------------
extern "C" void kernel_launch(void* const* d_in, const int* in_sizes, int n_in,
                              void* d_out, int out_size)
{
    (void)in_sizes; (void)n_in; (void)out_size;
    const float* x    = (const float*)d_in[0];
    const float* ln1g = (const float*)d_in[1];
    const float* ln1b = (const float*)d_in[2];
    const float* ln2g = (const float*)d_in[3];
    const float* ln2b = (const float*)d_in[4];
    const float* Wq   = (const float*)d_in[5];
    const float* bq   = (const float*)d_in[6];
    const float* Wk   = (const float*)d_in[7];
    const float* bk   = (const float*)d_in[8];
    const float* Wv   = (const float*)d_in[9];
    const float* bv   = (const float*)d_in[10];
    const float* W1   = (const float*)d_in[11];
    const float* b1   = (const float*)d_in[12];
    const float* W2   = (const float*)d_in[13];
    const float* b2   = (const float*)d_in[14];
    float* out = (float*)d_out;

    float *hp, *q, *k, *v, *x1, *m1, *wq, *wk, *wv, *w1, *w2;
    cudaGetSymbolAddress((void**)&hp, g_hp);
    cudaGetSymbolAddress((void**)&q,  g_q);
    cudaGetSymbolAddress((void**)&k,  g_k);
    cudaGetSymbolAddress((void**)&v,  g_v);
    cudaGetSymbolAddress((void**)&x1, g_x1);
    cudaGetSymbolAddress((void**)&m1, g_m1);
    cudaGetSymbolAddress((void**)&wq, g_wq);
    cudaGetSymbolAddress((void**)&wk, g_wk);
    cudaGetSymbolAddress((void**)&wv, g_wv);
    cudaGetSymbolAddress((void**)&w1, g_w1);
    cudaGetSymbolAddress((void**)&w2, g_w2);

    cudaFuncSetAttribute(attn_kernel,
                         cudaFuncAttributeMaxDynamicSharedMemorySize, (int)ATTN_SMEM);
    cudaFuncSetAttribute(gemm_mma<EPI_QKV>,
                         cudaFuncAttributeMaxDynamicSharedMemorySize, GEMM_SMEM);
    cudaFuncSetAttribute(gemm_mma<EPI_GELU>,
                         cudaFuncAttributeMaxDynamicSharedMemorySize, GEMM_SMEM);
    cudaFuncSetAttribute(gemm_mma<EPI_RES>,
                         cudaFuncAttributeMaxDynamicSharedMemorySize, GEMM_SMEM);

    // weight prep: permute + tf32-round into B-fragment order
    prep_w<<<dim3(32, 8),  256>>>(Wq, wq, HH);
    prep_w<<<dim3(32, 8),  256>>>(Wk, wk, HH);
    prep_w<<<dim3(32, 8),  256>>>(Wv, wv, HH);
    prep_w<<<dim3(32, 32), 256>>>(W1, w1, 4 * HH);
    prep_w<<<dim3(128, 8), 256>>>(W2, w2, HH);

    // LN1 -> hp (A-fragment order)
    ln_kernel<<<ROWS, 256>>>(x, ln1g, ln1b, hp);
    // QKV projections (head-permuted stores)
    dim3 gqkv(HH / 128, ROWS / 128);
    gemm_mma<EPI_QKV><<<gqkv, 256, GEMM_SMEM>>>(hp, wq, bq, nullptr, q, HH, HH);
    gemm_mma<EPI_QKV><<<gqkv, 256, GEMM_SMEM>>>(hp, wk, bk, nullptr, k, HH, HH);
    gemm_mma<EPI_QKV><<<gqkv, 256, GEMM_SMEM>>>(hp, wv, bv, nullptr, v, HH, HH);
    // attention + residual
    attn_kernel<<<dim3(TT / 64, NHEAD, BB), 256, ATTN_SMEM>>>(q, k, v, x, x1);
    // LN2 -> hp (A-fragment order)
    ln_kernel<<<ROWS, 256>>>(x1, ln2g, ln2b, hp);
    // MLP: W1 gemm writes m1 in A-fragment order; W2 gemm reads it back
    gemm_mma<EPI_GELU><<<dim3(4 * HH / 128, ROWS / 128), 256, GEMM_SMEM>>>(
        hp, w1, b1, nullptr, m1, 4 * HH, HH);
    gemm_mma<EPI_RES><<<dim3(HH / 128, ROWS / 128), 256, GEMM_SMEM>>>(
        m1, w2, b2, x1, out, HH, 4 * HH);
}

// round 13
// speedup vs baseline: 2.9017x; 1.0432x over previous
#include <cuda_runtime.h>
#include <math.h>
#include <stdint.h>

// Problem constants
#define BB 4
#define TT 1024
#define HH 1024
#define NHEAD 16
#define HDIM 64
#define ROWS (BB*TT)          // 4096

// ---------------- scratch (no allocs allowed) ----------------
__device__ float g_hp  [ROWS*HH];       // LN out, A-fragment-order (KC=32)
__device__ float g_q   [ROWS*HH];       // [b][head][t][d]
__device__ float g_k   [ROWS*HH];
__device__ float g_v   [ROWS*HH];
__device__ float g_x1  [ROWS*HH];       // x + attn out (row-major)
__device__ float g_m1  [ROWS*4*HH];     // gelu out, A-fragment-order (KC=128)
__device__ float g_wqkv[3*HH*HH];       // Wq|Wk|Wv, B-fragment-order, N=3072
__device__ float g_w1  [HH*4*HH];
__device__ float g_w2  [4*HH*HH];

// ---------------- helpers ----------------
__device__ __forceinline__ float tf32r(float x) {
    uint32_t r;
    asm("cvt.rna.tf32.f32 %0, %1;" : "=r"(r) : "f"(x));
    return __uint_as_float(r);
}
__device__ __forceinline__ uint32_t smem_u32(const void* p) {
    uint32_t a;
    asm("{ .reg .u64 t; cvta.to.shared.u64 t, %1; cvt.u32.u64 %0, t; }"
        : "=r"(a) : "l"(p));
    return a;
}
__device__ __forceinline__ void mma8(float* d, const uint32_t* a, const uint32_t* b) {
    asm volatile(
        "mma.sync.aligned.m16n8k8.row.col.f32.tf32.tf32.f32 "
        "{%0,%1,%2,%3}, {%4,%5,%6,%7}, {%8,%9}, {%0,%1,%2,%3};"
        : "+f"(d[0]), "+f"(d[1]), "+f"(d[2]), "+f"(d[3])
        : "r"(a[0]), "r"(a[1]), "r"(a[2]), "r"(a[3]), "r"(b[0]), "r"(b[1]));
}
#define CP16(dst, src) \
    asm volatile("cp.async.cg.shared.global [%0], [%1], 16;" :: "r"(dst), "l"(src))
#define CP_COMMIT() asm volatile("cp.async.commit_group;")
#define CP_WAIT1()  asm volatile("cp.async.wait_group 1;")

// ============ fused weight prep: all 5 weights -> B-fragment-order + tf32 ============
// chunk (4096 floats) layout: [nt(16)][ks(4)][lane(32)][reg(2)]
// grid: [0,768) QKV (w=blk/256, nb=(blk%256)/32, kc=blk%32)
//       [768,1792) W1 (nb<32, kc<32)   [1792,2816) W2 (nb<8, kc<128)
__global__ __launch_bounds__(256) void prep_all(
    const float* __restrict__ Wq, const float* __restrict__ Wk,
    const float* __restrict__ Wv, const float* __restrict__ W1,
    const float* __restrict__ W2,
    float* __restrict__ wqkv, float* __restrict__ w1, float* __restrict__ w2)
{
    __shared__ float s[32 * 132];
    const int t = threadIdx.x, blk = blockIdx.x;
    const float* W; float* out; int N, kc, nb;
    if (blk < 768) {
        int w = blk >> 8, r = blk & 255;
        nb = r >> 5; kc = r & 31; N = HH;
        W = (w == 0) ? Wq : (w == 1) ? Wk : Wv;
        out = wqkv + ((size_t)(w * 8 + nb) * 32 + kc) * 4096;
    } else if (blk < 1792) {
        int r = blk - 768;
        nb = r >> 5; kc = r & 31; N = 4 * HH;
        W = W1; out = w1 + ((size_t)nb * 32 + kc) * 4096;
    } else {
        int r = blk - 1792;
        nb = r >> 7; kc = r & 127; N = HH;
        W = W2; out = w2 + ((size_t)nb * 128 + kc) * 4096;
    }
    const float* Wg = W + (size_t)(kc * 32) * N + nb * 128;
    #pragma unroll
    for (int i = 0; i < 4; i++) {
        int fl = t + i * 256;
        int r = fl >> 5, c4 = (fl & 31) << 2;
        float4 v = *(const float4*)(Wg + (size_t)r * N + c4);
        s[r * 132 + c4 + 0] = v.x; s[r * 132 + c4 + 1] = v.y;
        s[r * 132 + c4 + 2] = v.z; s[r * 132 + c4 + 3] = v.w;
    }
    __syncthreads();
    float* o = out + t * 16;
    #pragma unroll
    for (int j4 = 0; j4 < 4; j4++) {
        float4 v; float* vp = (float*)&v;
        #pragma unroll
        for (int e = 0; e < 4; e++) {
            int f = t * 16 + j4 * 4 + e;
            int nt = f >> 8, ks = (f >> 6) & 3, ln = (f >> 1) & 31, rg = f & 1;
            int k3 = rg * 4 + (ln & 3);
            int nl = nt * 8 + ((ln >> 4) << 2) + ((ln >> 2) & 3);
            vp[e] = tf32r(s[(ks * 8 + k3) * 132 + nl]);
        }
        *(float4*)(o + j4 * 4) = v;
    }
}

// ---------------- LayerNorm -> A-fragment-order output (KC=32) ----------------
__global__ __launch_bounds__(256) void ln_kernel(
    const float* __restrict__ x, const float* __restrict__ g,
    const float* __restrict__ b, float* __restrict__ out)
{
    __shared__ float red[8];
    const int row = blockIdx.x, tid = threadIdx.x;
    const float* xr = x + (size_t)row * HH;
    float4 v = *(const float4*)(xr + tid * 4);

    float s = v.x + v.y + v.z + v.w;
    #pragma unroll
    for (int o = 16; o > 0; o >>= 1) s += __shfl_xor_sync(0xffffffffu, s, o);
    if ((tid & 31) == 0) red[tid >> 5] = s;
    __syncthreads();
    float tot = red[0]+red[1]+red[2]+red[3]+red[4]+red[5]+red[6]+red[7];
    const float mu = tot * (1.0f / HH);

    float dx = v.x - mu, dy = v.y - mu, dz = v.z - mu, dw = v.w - mu;
    float ss = dx*dx + dy*dy + dz*dz + dw*dw;
    #pragma unroll
    for (int o = 16; o > 0; o >>= 1) ss += __shfl_xor_sync(0xffffffffu, ss, o);
    __syncthreads();
    if ((tid & 31) == 0) red[tid >> 5] = ss;
    __syncthreads();
    float tot2 = red[0]+red[1]+red[2]+red[3]+red[4]+red[5]+red[6]+red[7];
    const float rs = rsqrtf(tot2 * (1.0f / HH) + 1e-5f);

    float4 gv = *(const float4*)(g + tid * 4);
    float4 bv = *(const float4*)(b + tid * 4);
    float o0 = dx * rs * gv.x + bv.x;
    float o1 = dy * rs * gv.y + bv.y;
    float o2 = dz * rs * gv.z + bv.z;
    float o3 = dw * rs * gv.w + bv.w;

    // scatter into A-fragment order (k = 4*tid .. 4*tid+3)
    const int mb = row >> 7, mt = (row >> 4) & 7, hi = (row >> 3) & 1, gg = row & 7;
    const int kc = tid >> 3, ks = (tid >> 1) & 3, chi = tid & 1;
    float* op = out + ((size_t)(mb * 32 + kc)) * 4096
              + (mt * 4 + ks) * 128 + gg * 16 + hi + 2 * chi;
    op[0]  = tf32r(o0);
    op[4]  = tf32r(o1);
    op[8]  = tf32r(o2);
    op[12] = tf32r(o3);
}

// ============ tf32 mma.sync GEMM: 128x128 CTA, 4 warps of 64x64, 3-stage ============
enum { EPI_QKV = 0, EPI_GELU = 1, EPI_RES = 2 };

#define GEMM_SMEM (3 * 8192 * 4)   // 96 KB: 3 stages x (A 16KB + B 16KB)

template <int EPI>
__global__ __launch_bounds__(128, 2) void gemm_mma(
    const float* __restrict__ Ap, const float* __restrict__ Bp,
    const float* __restrict__ bias, const float* __restrict__ bias2,
    const float* __restrict__ bias3, const float* __restrict__ resid,
    float* __restrict__ C, float* __restrict__ C2, float* __restrict__ C3,
    int N, int Kd)
{
    extern __shared__ __align__(16) float smem[];   // [3][8192]
    const int tid = threadIdx.x, lane = tid & 31, wid = tid >> 5;
    const int wm = wid & 1, wn = wid >> 1;          // 2 x 2 warp grid, 64x64 tiles
    const int gl = lane >> 2, cl = lane & 3;
    const int bn = blockIdx.x * 128, bm = blockIdx.y * 128;
    const int KC = Kd >> 5;
    const float* Ach = Ap + (size_t)blockIdx.y * KC * 4096;
    const float* Bch = Bp + (size_t)blockIdx.x * KC * 4096;
    const uint32_t sb = smem_u32(smem);

    float acc[4][8][4];
    #pragma unroll
    for (int mi = 0; mi < 4; mi++)
        #pragma unroll
        for (int ni = 0; ni < 8; ni++)
            #pragma unroll
            for (int r = 0; r < 4; r++) acc[mi][ni][r] = 0.f;

    auto issue = [&](int st, int kc) {
        if (kc < KC) {
            const float* As = Ach + (size_t)kc * 4096;
            const float* Bs = Bch + (size_t)kc * 4096;
            uint32_t da = sb + st * 32768;
            uint32_t db = da + 16384;
            #pragma unroll
            for (int i = 0; i < 8; i++) {
                int fl = (tid + i * 128) * 4;        // float index
                CP16(da + fl * 4, As + fl);
                CP16(db + fl * 4, Bs + fl);
            }
        }
        CP_COMMIT();
    };

    issue(0, 0);
    issue(1, 1);
    for (int kc = 0; kc < KC; kc++) {
        CP_WAIT1();
        __syncthreads();
        issue((kc + 2) % 3, kc + 2);
        const float* sA = smem + (kc % 3) * 8192;
        const float* sB = sA + 4096;
        #pragma unroll
        for (int ks = 0; ks < 4; ks++) {
            uint32_t af[4][4];
            uint32_t bf[8][2];
            #pragma unroll
            for (int mi = 0; mi < 4; mi++) {
                int mt = wm * 4 + mi;
                *(uint4*)af[mi] =
                    *(const uint4*)&sA[((mt << 2) + ks) * 128 + (lane << 2)];
            }
            #pragma unroll
            for (int ni = 0; ni < 8; ni++) {
                int nt = wn * 8 + ni;
                *(uint2*)bf[ni] =
                    *(const uint2*)&sB[((nt << 2) + ks) * 64 + (lane << 1)];
            }
            #pragma unroll
            for (int mi = 0; mi < 4; mi++)
                #pragma unroll
                for (int ni = 0; ni < 8; ni++)
                    mma8(acc[mi][ni], af[mi], bf[ni]);
        }
    }

    // ---- epilogue ----
    // QKV fused: N=3072, block's 128-col span lies in exactly one of q/k/v
    const float* bs = bias;
    float* Cd = C;
    int bnl = bn;
    if (EPI == EPI_QKV) {
        const int which = bn >> 10;
        bs  = (which == 0) ? bias : (which == 1) ? bias2 : bias3;
        Cd  = (which == 0) ? C    : (which == 1) ? C2    : C3;
        bnl = bn & 1023;
    }
    #pragma unroll
    for (int mi = 0; mi < 4; mi++) {
        const int r0 = bm + wm * 64 + mi * 16 + gl;   // second half row r0+8
        #pragma unroll
        for (int ni = 0; ni < 8; ni++) {
            const int colw = wn * 64 + ni * 8 + (cl << 1);
            const int col = (EPI == EPI_QKV) ? (bnl + colw) : (bn + colw);
            const float bx = __ldg(&bs[col]);
            const float by = __ldg(&bs[col + 1]);
            float v00 = acc[mi][ni][0] + bx, v01 = acc[mi][ni][1] + by;
            float v10 = acc[mi][ni][2] + bx, v11 = acc[mi][ni][3] + by;
            if (EPI == EPI_QKV) {
                const int head = col >> 6, d0 = col & 63;
                #pragma unroll
                for (int hh2 = 0; hh2 < 2; hh2++) {
                    const int row = r0 + hh2 * 8;
                    float* Cp = Cd + ((size_t)((row >> 10) * NHEAD + head)) * (TT * HDIM)
                                   + (size_t)(row & (TT - 1)) * HDIM + d0;
                    float2 o = hh2 ? make_float2(v10, v11) : make_float2(v00, v01);
                    *(float2*)Cp = o;
                }
            } else if (EPI == EPI_GELU) {
                float t00 = 0.5f * v00 * (1.0f + erff(v00 * 0.70710678118654752f));
                float t01 = 0.5f * v01 * (1.0f + erff(v01 * 0.70710678118654752f));
                float t10 = 0.5f * v10 * (1.0f + erff(v10 * 0.70710678118654752f));
                float t11 = 0.5f * v11 * (1.0f + erff(v11 * 0.70710678118654752f));
                size_t idx = ((size_t)((r0 >> 7) * 128 + (col >> 5))) * 4096
                           + ((((r0 >> 4) & 7) << 2) + ((col >> 3) & 3)) * 128
                           + (((r0 & 7) << 2) + (col & 3)) * 4
                           + ((col >> 2) & 1) * 2;
                *(float2*)(Cd + idx)     = make_float2(tf32r(t00), tf32r(t10));
                *(float2*)(Cd + idx + 4) = make_float2(tf32r(t01), tf32r(t11));
            } else {
                float2 ra = *(const float2*)(resid + (size_t)r0 * N + col);
                float2 rb = *(const float2*)(resid + (size_t)(r0 + 8) * N + col);
                *(float2*)(Cd + (size_t)r0 * N + col) =
                    make_float2(v00 + ra.x, v01 + ra.y);
                *(float2*)(Cd + (size_t)(r0 + 8) * N + col) =
                    make_float2(v10 + rb.x, v11 + rb.y);
            }
        }
    }
}

// ---------------- Attention with 1e-9 mask fill, fused residual ----------------
// Flash loop over kt <= qt only; fully-masked tiles folded in analytically.
#define ST 68
#define ATTN_SMEM (size_t)((4 * 64 * ST + 3 * 64) * sizeof(float))

__global__ __launch_bounds__(256) void attn_kernel(
    const float* __restrict__ q, const float* __restrict__ k,
    const float* __restrict__ v, const float* __restrict__ x,
    float* __restrict__ x1)
{
    extern __shared__ __align__(16) char smem_raw[];
    float* sm = (float*)smem_raw;
    float* Qs = sm;
    float* Ks = Qs + 64 * ST;
    float* Vs = Ks + 64 * ST;
    float* Ss = Vs + 64 * ST;       // scores / probs; reused as vpart after loop
    float* mrow = Ss + 64 * ST;     // running max; reused as e after loop
    float* lrow = mrow + 64;
    float* arow = lrow + 64;

    const int tid = threadIdx.x;
    const int tx = tid & 15, ty = tid >> 4;
    const int qt = blockIdx.x, head = blockIdx.y, b = blockIdx.z;
    const int qg0 = qt * 64;

    const float* Qg = q + (size_t)((b * NHEAD + head) * TT + qg0) * HDIM;
    const float* Kg = k + (size_t)(b * NHEAD + head) * TT * HDIM;
    const float* Vg = v + (size_t)(b * NHEAD + head) * TT * HDIM;

    for (int i = tid; i < 64 * 16; i += 256) {
        int r = i >> 4, c4 = (i & 15) << 2;
        *(float4*)&Qs[r * ST + c4] = *(const float4*)&Qg[r * 64 + c4];
    }
    if (tid < 64) { mrow[tid] = -1e30f; lrow[tid] = 0.f; }

    float acc[4][4];
    #pragma unroll
    for (int i = 0; i < 4; i++)
        #pragma unroll
        for (int j = 0; j < 4; j++) acc[i][j] = 0.f;

    for (int kt = 0; kt <= qt; kt++) {
        __syncthreads();
        const float* Kt = Kg + (size_t)kt * 64 * 64;
        const float* Vt = Vg + (size_t)kt * 64 * 64;
        for (int i = tid; i < 64 * 16; i += 256) {
            int r = i >> 4, c4 = (i & 15) << 2;
            *(float4*)&Ks[r * ST + c4] = *(const float4*)&Kt[r * 64 + c4];
            *(float4*)&Vs[r * ST + c4] = *(const float4*)&Vt[r * 64 + c4];
        }
        __syncthreads();

        const int kp0 = kt * 64;
        {
            float sacc[4][4];
            #pragma unroll
            for (int qi = 0; qi < 4; qi++)
                #pragma unroll
                for (int ki = 0; ki < 4; ki++) sacc[qi][ki] = 0.f;
            #pragma unroll 4
            for (int d = 0; d < 64; d += 4) {
                float4 qv[4], kv[4];
                #pragma unroll
                for (int qi = 0; qi < 4; qi++)
                    qv[qi] = *(const float4*)&Qs[(ty * 4 + qi) * ST + d];
                #pragma unroll
                for (int ki = 0; ki < 4; ki++)
                    kv[ki] = *(const float4*)&Ks[(tx * 4 + ki) * ST + d];
                #pragma unroll
                for (int qi = 0; qi < 4; qi++)
                    #pragma unroll
                    for (int ki = 0; ki < 4; ki++) {
                        sacc[qi][ki] += qv[qi].x * kv[ki].x;
                        sacc[qi][ki] += qv[qi].y * kv[ki].y;
                        sacc[qi][ki] += qv[qi].z * kv[ki].z;
                        sacc[qi][ki] += qv[qi].w * kv[ki].w;
                    }
            }
            #pragma unroll
            for (int qi = 0; qi < 4; qi++)
                #pragma unroll
                for (int ki = 0; ki < 4; ki++) {
                    int qq = ty * 4 + qi, kk = tx * 4 + ki;
                    float s = sacc[qi][ki] * 0.125f;
                    if (kp0 + kk > qg0 + qq) s = 1e-9f;   // diagonal-tile mask FILL
                    Ss[qq * ST + kk] = s;
                }
        }
        __syncthreads();

        if (tid < 64) {
            float mo = mrow[tid], mn = mo;
            const float* srow = &Ss[tid * ST];
            #pragma unroll 8
            for (int p = 0; p < 64; p++) mn = fmaxf(mn, srow[p]);
            arow[tid] = __expf(mo - mn);
            mrow[tid] = mn;
        }
        __syncthreads();

        #pragma unroll
        for (int qi = 0; qi < 4; qi++) {
            int qq = ty * 4 + qi;
            float mq = mrow[qq];
            #pragma unroll
            for (int ki = 0; ki < 4; ki++) {
                int kk = tx * 4 + ki;
                Ss[qq * ST + kk] = __expf(Ss[qq * ST + kk] - mq);
            }
        }
        __syncthreads();

        if (tid < 64) {
            float s = 0.f;
            const float* srow = &Ss[tid * ST];
            #pragma unroll 8
            for (int p = 0; p < 64; p++) s += srow[p];
            lrow[tid] = lrow[tid] * arow[tid] + s;
        }
        float al[4];
        #pragma unroll
        for (int qi = 0; qi < 4; qi++) al[qi] = arow[ty * 4 + qi];
        #pragma unroll
        for (int qi = 0; qi < 4; qi++)
            #pragma unroll
            for (int di = 0; di < 4; di++) acc[qi][di] *= al[qi];
        #pragma unroll 4
        for (int p = 0; p < 64; p += 4) {
            float4 vv0 = *(const float4*)&Vs[(p + 0) * ST + tx * 4];
            float4 vv1 = *(const float4*)&Vs[(p + 1) * ST + tx * 4];
            float4 vv2 = *(const float4*)&Vs[(p + 2) * ST + tx * 4];
            float4 vv3 = *(const float4*)&Vs[(p + 3) * ST + tx * 4];
            #pragma unroll
            for (int qi = 0; qi < 4; qi++) {
                float4 pw = *(const float4*)&Ss[(ty * 4 + qi) * ST + p];
                acc[qi][0] += pw.x * vv0.x + pw.y * vv1.x + pw.z * vv2.x + pw.w * vv3.x;
                acc[qi][1] += pw.x * vv0.y + pw.y * vv1.y + pw.z * vv2.y + pw.w * vv3.y;
                acc[qi][2] += pw.x * vv0.z + pw.y * vv1.z + pw.z * vv2.z + pw.w * vv3.z;
                acc[qi][3] += pw.x * vv0.w + pw.y * vv1.w + pw.z * vv2.w + pw.w * vv3.w;
            }
        }
    }
    __syncthreads();   // mainloop done; Ss free for reuse

    // ---- virtual masked tile: rows [(qt+1)*64, 1024) all have score 1e-9 ----
    if (qt < 15) {
        const int mstart = (qt + 1) * 64;
        const float nmask = (float)(TT - mstart);
        float* vpart = Ss;                   // reuse: [4][64]
        {
            float ps = 0.f;
            const int col = tid & 63, seg = tid >> 6;
            for (int r = mstart + seg; r < TT; r += 4)
                ps += Vg[(size_t)r * 64 + col];
            vpart[seg * 64 + col] = ps;
        }
        if (tid < 64) {
            float mo = mrow[tid], mn = fmaxf(mo, 1e-9f);
            float a = __expf(mo - mn);
            float e = __expf(1e-9f - mn);
            arow[tid] = a;
            mrow[tid] = e;
            lrow[tid] = lrow[tid] * a + nmask * e;
        }
        __syncthreads();
        float al[4], el[4];
        #pragma unroll
        for (int qi = 0; qi < 4; qi++) {
            al[qi] = arow[ty * 4 + qi];
            el[qi] = mrow[ty * 4 + qi];
        }
        float vs[4];
        #pragma unroll
        for (int di = 0; di < 4; di++) {
            int col = tx * 4 + di;
            vs[di] = vpart[col] + vpart[64 + col] + vpart[128 + col] + vpart[192 + col];
        }
        #pragma unroll
        for (int qi = 0; qi < 4; qi++)
            #pragma unroll
            for (int di = 0; di < 4; di++)
                acc[qi][di] = acc[qi][di] * al[qi] + el[qi] * vs[di];
        __syncthreads();
    }

    // epilogue: x1 = x + y   (y back to [b][t][H] layout)
    #pragma unroll
    for (int qi = 0; qi < 4; qi++) {
        int qq = ty * 4 + qi;
        float inv = 1.0f / lrow[qq];
        size_t base = ((size_t)(b * TT + qg0 + qq)) * HH + head * HDIM + tx * 4;
        #pragma unroll
        for (int di = 0; di < 4; di++)
            x1[base + di] = x[base + di] + acc[qi][di] * inv;
    }
}

// ---------------- launch ----------------
extern "C" void kernel_launch(void* const* d_in, const int* in_sizes, int n_in,
                              void* d_out, int out_size)
{
    (void)in_sizes; (void)n_in; (void)out_size;
    const float* x    = (const float*)d_in[0];
    const float* ln1g = (const float*)d_in[1];
    const float* ln1b = (const float*)d_in[2];
    const float* ln2g = (const float*)d_in[3];
    const float* ln2b = (const float*)d_in[4];
    const float* Wq   = (const float*)d_in[5];
    const float* bq   = (const float*)d_in[6];
    const float* Wk   = (const float*)d_in[7];
    const float* bk   = (const float*)d_in[8];
    const float* Wv   = (const float*)d_in[9];
    const float* bv   = (const float*)d_in[10];
    const float* W1   = (const float*)d_in[11];
    const float* b1   = (const float*)d_in[12];
    const float* W2   = (const float*)d_in[13];
    const float* b2   = (const float*)d_in[14];
    float* out = (float*)d_out;

    float *hp, *q, *k, *v, *x1, *m1, *wqkv, *w1, *w2;
    cudaGetSymbolAddress((void**)&hp,   g_hp);
    cudaGetSymbolAddress((void**)&q,    g_q);
    cudaGetSymbolAddress((void**)&k,    g_k);
    cudaGetSymbolAddress((void**)&v,    g_v);
    cudaGetSymbolAddress((void**)&x1,   g_x1);
    cudaGetSymbolAddress((void**)&m1,   g_m1);
    cudaGetSymbolAddress((void**)&wqkv, g_wqkv);
    cudaGetSymbolAddress((void**)&w1,   g_w1);
    cudaGetSymbolAddress((void**)&w2,   g_w2);

    cudaFuncSetAttribute(attn_kernel,
                         cudaFuncAttributeMaxDynamicSharedMemorySize, (int)ATTN_SMEM);
    cudaFuncSetAttribute(gemm_mma<EPI_QKV>,
                         cudaFuncAttributeMaxDynamicSharedMemorySize, GEMM_SMEM);
    cudaFuncSetAttribute(gemm_mma<EPI_GELU>,
                         cudaFuncAttributeMaxDynamicSharedMemorySize, GEMM_SMEM);
    cudaFuncSetAttribute(gemm_mma<EPI_RES>,
                         cudaFuncAttributeMaxDynamicSharedMemorySize, GEMM_SMEM);

    // fused weight prep (all 5 weights, one launch)
    prep_all<<<2816, 256>>>(Wq, Wk, Wv, W1, W2, wqkv, w1, w2);

    // LN1 -> hp (A-fragment order)
    ln_kernel<<<ROWS, 256>>>(x, ln1g, ln1b, hp);
    // fused QKV projection: N=3072, head-permuted stores into q/k/v
    gemm_mma<EPI_QKV><<<dim3(3 * HH / 128, ROWS / 128), 128, GEMM_SMEM>>>(
        hp, wqkv, bq, bk, bv, nullptr, q, k, v, 3 * HH, HH);
    // attention + residual
    attn_kernel<<<dim3(TT / 64, NHEAD, BB), 256, ATTN_SMEM>>>(q, k, v, x, x1);
    // LN2 -> hp (A-fragment order)
    ln_kernel<<<ROWS, 256>>>(x1, ln2g, ln2b, hp);
    // MLP: W1 gemm writes m1 in A-fragment order; W2 gemm reads it back
    gemm_mma<EPI_GELU><<<dim3(4 * HH / 128, ROWS / 128), 128, GEMM_SMEM>>>(
        hp, w1, b1, nullptr, nullptr, nullptr, m1, nullptr, nullptr, 4 * HH, HH);
    gemm_mma<EPI_RES><<<dim3(HH / 128, ROWS / 128), 128, GEMM_SMEM>>>(
        m1, w2, b2, nullptr, nullptr, x1, out, nullptr, nullptr, HH, 4 * HH);
}

// round 14
// speedup vs baseline: 4.8056x; 1.6561x over previous
#include <cuda_runtime.h>
#include <math.h>
#include <stdint.h>

// Problem constants
#define BB 4
#define TT 1024
#define HH 1024
#define NHEAD 16
#define HDIM 64
#define ROWS (BB*TT)          // 4096

// ---------------- scratch (no allocs allowed) ----------------
__device__ float g_hp  [ROWS*HH];       // LN out, A-fragment-order (KC=32)
__device__ float g_q   [ROWS*HH];       // [b][head][t][d]
__device__ float g_k   [ROWS*HH];
__device__ float g_v   [ROWS*HH];
__device__ float g_x1  [ROWS*HH];       // x + attn out (row-major)
__device__ float g_m1  [ROWS*4*HH];     // gelu out, A-fragment-order (KC=128)
__device__ float g_wqkv[3*HH*HH];       // Wq|Wk|Wv, B-fragment-order, N=3072
__device__ float g_w1  [HH*4*HH];
__device__ float g_w2  [4*HH*HH];

// ---------------- helpers ----------------
__device__ __forceinline__ float tf32r(float x) {
    uint32_t r;
    asm("cvt.rna.tf32.f32 %0, %1;" : "=r"(r) : "f"(x));
    return __uint_as_float(r);
}
__device__ __forceinline__ uint32_t smem_u32(const void* p) {
    uint32_t a;
    asm("{ .reg .u64 t; cvta.to.shared.u64 t, %1; cvt.u32.u64 %0, t; }"
        : "=r"(a) : "l"(p));
    return a;
}
__device__ __forceinline__ void mma8(float* d, const uint32_t* a, const uint32_t* b) {
    asm volatile(
        "mma.sync.aligned.m16n8k8.row.col.f32.tf32.tf32.f32 "
        "{%0,%1,%2,%3}, {%4,%5,%6,%7}, {%8,%9}, {%0,%1,%2,%3};"
        : "+f"(d[0]), "+f"(d[1]), "+f"(d[2]), "+f"(d[3])
        : "r"(a[0]), "r"(a[1]), "r"(a[2]), "r"(a[3]), "r"(b[0]), "r"(b[1]));
}
#define CP16(dst, src) \
    asm volatile("cp.async.cg.shared.global [%0], [%1], 16;" :: "r"(dst), "l"(src))
#define CP_COMMIT() asm volatile("cp.async.commit_group;")
#define CP_WAIT1()  asm volatile("cp.async.wait_group 1;")

// ============ fused weight prep: all 5 weights -> B-fragment-order + tf32 ============
__global__ __launch_bounds__(256) void prep_all(
    const float* __restrict__ Wq, const float* __restrict__ Wk,
    const float* __restrict__ Wv, const float* __restrict__ W1,
    const float* __restrict__ W2,
    float* __restrict__ wqkv, float* __restrict__ w1, float* __restrict__ w2)
{
    __shared__ float s[32 * 132];
    const int t = threadIdx.x, blk = blockIdx.x;
    const float* W; float* out; int N, kc, nb;
    if (blk < 768) {
        int w = blk >> 8, r = blk & 255;
        nb = r >> 5; kc = r & 31; N = HH;
        W = (w == 0) ? Wq : (w == 1) ? Wk : Wv;
        out = wqkv + ((size_t)(w * 8 + nb) * 32 + kc) * 4096;
    } else if (blk < 1792) {
        int r = blk - 768;
        nb = r >> 5; kc = r & 31; N = 4 * HH;
        W = W1; out = w1 + ((size_t)nb * 32 + kc) * 4096;
    } else {
        int r = blk - 1792;
        nb = r >> 7; kc = r & 127; N = HH;
        W = W2; out = w2 + ((size_t)nb * 128 + kc) * 4096;
    }
    const float* Wg = W + (size_t)(kc * 32) * N + nb * 128;
    #pragma unroll
    for (int i = 0; i < 4; i++) {
        int fl = t + i * 256;
        int r = fl >> 5, c4 = (fl & 31) << 2;
        float4 v = *(const float4*)(Wg + (size_t)r * N + c4);
        s[r * 132 + c4 + 0] = v.x; s[r * 132 + c4 + 1] = v.y;
        s[r * 132 + c4 + 2] = v.z; s[r * 132 + c4 + 3] = v.w;
    }
    __syncthreads();
    float* o = out + t * 16;
    #pragma unroll
    for (int j4 = 0; j4 < 4; j4++) {
        float4 v; float* vp = (float*)&v;
        #pragma unroll
        for (int e = 0; e < 4; e++) {
            int f = t * 16 + j4 * 4 + e;
            int nt = f >> 8, ks = (f >> 6) & 3, ln = (f >> 1) & 31, rg = f & 1;
            int k3 = rg * 4 + (ln & 3);
            int nl = nt * 8 + ((ln >> 4) << 2) + ((ln >> 2) & 3);
            vp[e] = tf32r(s[(ks * 8 + k3) * 132 + nl]);
        }
        *(float4*)(o + j4 * 4) = v;
    }
}

// ---------------- LayerNorm -> A-fragment-order output (KC=32) ----------------
__global__ __launch_bounds__(256) void ln_kernel(
    const float* __restrict__ x, const float* __restrict__ g,
    const float* __restrict__ b, float* __restrict__ out)
{
    __shared__ float red[8];
    const int row = blockIdx.x, tid = threadIdx.x;
    const float* xr = x + (size_t)row * HH;
    float4 v = *(const float4*)(xr + tid * 4);

    float s = v.x + v.y + v.z + v.w;
    #pragma unroll
    for (int o = 16; o > 0; o >>= 1) s += __shfl_xor_sync(0xffffffffu, s, o);
    if ((tid & 31) == 0) red[tid >> 5] = s;
    __syncthreads();
    float tot = red[0]+red[1]+red[2]+red[3]+red[4]+red[5]+red[6]+red[7];
    const float mu = tot * (1.0f / HH);

    float dx = v.x - mu, dy = v.y - mu, dz = v.z - mu, dw = v.w - mu;
    float ss = dx*dx + dy*dy + dz*dz + dw*dw;
    #pragma unroll
    for (int o = 16; o > 0; o >>= 1) ss += __shfl_xor_sync(0xffffffffu, ss, o);
    __syncthreads();
    if ((tid & 31) == 0) red[tid >> 5] = ss;
    __syncthreads();
    float tot2 = red[0]+red[1]+red[2]+red[3]+red[4]+red[5]+red[6]+red[7];
    const float rs = rsqrtf(tot2 * (1.0f / HH) + 1e-5f);

    float4 gv = *(const float4*)(g + tid * 4);
    float4 bv = *(const float4*)(b + tid * 4);
    float o0 = dx * rs * gv.x + bv.x;
    float o1 = dy * rs * gv.y + bv.y;
    float o2 = dz * rs * gv.z + bv.z;
    float o3 = dw * rs * gv.w + bv.w;

    const int mb = row >> 7, mt = (row >> 4) & 7, hi = (row >> 3) & 1, gg = row & 7;
    const int kc = tid >> 3, ks = (tid >> 1) & 3, chi = tid & 1;
    float* op = out + ((size_t)(mb * 32 + kc)) * 4096
              + (mt * 4 + ks) * 128 + gg * 16 + hi + 2 * chi;
    op[0]  = tf32r(o0);
    op[4]  = tf32r(o1);
    op[8]  = tf32r(o2);
    op[12] = tf32r(o3);
}

// ============ tf32 mma.sync GEMM: 128x128 CTA, 4 warps of 64x64, 3-stage ============
enum { EPI_QKV = 0, EPI_GELU = 1, EPI_RES = 2 };

#define GEMM_SMEM (3 * 8192 * 4)   // 96 KB

template <int EPI>
__global__ __launch_bounds__(128, 2) void gemm_mma(
    const float* __restrict__ Ap, const float* __restrict__ Bp,
    const float* __restrict__ bias, const float* __restrict__ bias2,
    const float* __restrict__ bias3, const float* __restrict__ resid,
    float* __restrict__ C, float* __restrict__ C2, float* __restrict__ C3,
    int N, int Kd)
{
    extern __shared__ __align__(16) float smem[];   // [3][8192]
    const int tid = threadIdx.x, lane = tid & 31, wid = tid >> 5;
    const int wm = wid & 1, wn = wid >> 1;          // 2 x 2 warp grid, 64x64 tiles
    const int gl = lane >> 2, cl = lane & 3;
    const int bn = blockIdx.x * 128, bm = blockIdx.y * 128;
    const int KC = Kd >> 5;
    const float* Ach = Ap + (size_t)blockIdx.y * KC * 4096;
    const float* Bch = Bp + (size_t)blockIdx.x * KC * 4096;
    const uint32_t sb = smem_u32(smem);

    float acc[4][8][4];
    #pragma unroll
    for (int mi = 0; mi < 4; mi++)
        #pragma unroll
        for (int ni = 0; ni < 8; ni++)
            #pragma unroll
            for (int r = 0; r < 4; r++) acc[mi][ni][r] = 0.f;

    auto issue = [&](int st, int kc) {
        if (kc < KC) {
            const float* As = Ach + (size_t)kc * 4096;
            const float* Bs = Bch + (size_t)kc * 4096;
            uint32_t da = sb + st * 32768;
            uint32_t db = da + 16384;
            #pragma unroll
            for (int i = 0; i < 8; i++) {
                int fl = (tid + i * 128) * 4;
                CP16(da + fl * 4, As + fl);
                CP16(db + fl * 4, Bs + fl);
            }
        }
        CP_COMMIT();
    };

    issue(0, 0);
    issue(1, 1);
    for (int kc = 0; kc < KC; kc++) {
        CP_WAIT1();
        __syncthreads();
        issue((kc + 2) % 3, kc + 2);
        const float* sA = smem + (kc % 3) * 8192;
        const float* sB = sA + 4096;
        #pragma unroll
        for (int ks = 0; ks < 4; ks++) {
            uint32_t af[4][4];
            uint32_t bf[8][2];
            #pragma unroll
            for (int mi = 0; mi < 4; mi++) {
                int mt = wm * 4 + mi;
                *(uint4*)af[mi] =
                    *(const uint4*)&sA[((mt << 2) + ks) * 128 + (lane << 2)];
            }
            #pragma unroll
            for (int ni = 0; ni < 8; ni++) {
                int nt = wn * 8 + ni;
                *(uint2*)bf[ni] =
                    *(const uint2*)&sB[((nt << 2) + ks) * 64 + (lane << 1)];
            }
            #pragma unroll
            for (int mi = 0; mi < 4; mi++)
                #pragma unroll
                for (int ni = 0; ni < 8; ni++)
                    mma8(acc[mi][ni], af[mi], bf[ni]);
        }
    }

    // ---- epilogue ----
    const float* bs = bias;
    float* Cd = C;
    int bnl = bn;
    if (EPI == EPI_QKV) {
        const int which = bn >> 10;
        bs  = (which == 0) ? bias : (which == 1) ? bias2 : bias3;
        Cd  = (which == 0) ? C    : (which == 1) ? C2    : C3;
        bnl = bn & 1023;
    }
    #pragma unroll
    for (int mi = 0; mi < 4; mi++) {
        const int r0 = bm + wm * 64 + mi * 16 + gl;
        #pragma unroll
        for (int ni = 0; ni < 8; ni++) {
            const int colw = wn * 64 + ni * 8 + (cl << 1);
            const int col = (EPI == EPI_QKV) ? (bnl + colw) : (bn + colw);
            const float bx = __ldg(&bs[col]);
            const float by = __ldg(&bs[col + 1]);
            float v00 = acc[mi][ni][0] + bx, v01 = acc[mi][ni][1] + by;
            float v10 = acc[mi][ni][2] + bx, v11 = acc[mi][ni][3] + by;
            if (EPI == EPI_QKV) {
                const int head = col >> 6, d0 = col & 63;
                #pragma unroll
                for (int hh2 = 0; hh2 < 2; hh2++) {
                    const int row = r0 + hh2 * 8;
                    float* Cp = Cd + ((size_t)((row >> 10) * NHEAD + head)) * (TT * HDIM)
                                   + (size_t)(row & (TT - 1)) * HDIM + d0;
                    float2 o = hh2 ? make_float2(v10, v11) : make_float2(v00, v01);
                    *(float2*)Cp = o;
                }
            } else if (EPI == EPI_GELU) {
                float t00 = 0.5f * v00 * (1.0f + erff(v00 * 0.70710678118654752f));
                float t01 = 0.5f * v01 * (1.0f + erff(v01 * 0.70710678118654752f));
                float t10 = 0.5f * v10 * (1.0f + erff(v10 * 0.70710678118654752f));
                float t11 = 0.5f * v11 * (1.0f + erff(v11 * 0.70710678118654752f));
                size_t idx = ((size_t)((r0 >> 7) * 128 + (col >> 5))) * 4096
                           + ((((r0 >> 4) & 7) << 2) + ((col >> 3) & 3)) * 128
                           + (((r0 & 7) << 2) + (col & 3)) * 4
                           + ((col >> 2) & 1) * 2;
                *(float2*)(Cd + idx)     = make_float2(tf32r(t00), tf32r(t10));
                *(float2*)(Cd + idx + 4) = make_float2(tf32r(t01), tf32r(t11));
            } else {
                float2 ra = *(const float2*)(resid + (size_t)r0 * N + col);
                float2 rb = *(const float2*)(resid + (size_t)(r0 + 8) * N + col);
                *(float2*)(Cd + (size_t)r0 * N + col) =
                    make_float2(v00 + ra.x, v01 + ra.y);
                *(float2*)(Cd + (size_t)(r0 + 8) * N + col) =
                    make_float2(v10 + rb.x, v11 + rb.y);
            }
        }
    }
}

// ======== Tensor-core attention: 4 warps x 16 q-rows, register softmax ========
// Strides: K/P smem stride 68 (fragment scalar LDS conflict-free: bank=4g+c),
// V stride 72 (PV B-frags bank=8c+g, conflict-free).
#define AST 68
#define VST 72
#define ATTN_SMEM (size_t)((64*AST + 64*VST + 64*AST) * sizeof(float))

__global__ __launch_bounds__(128, 3) void attn_tc(
    const float* __restrict__ q, const float* __restrict__ k,
    const float* __restrict__ v, const float* __restrict__ x,
    float* __restrict__ x1)
{
    extern __shared__ __align__(16) float sm[];
    float* Ks = sm;                 // 64 x AST (also Q staging)
    float* Vs = Ks + 64 * AST;      // 64 x VST
    float* Ps = Vs + 64 * VST;      // 64 x AST (P; vsum scratch after loop)

    const int tid = threadIdx.x, lane = tid & 31, w = tid >> 5;
    const int gl = lane >> 2, cl = lane & 3;
    const int qt = blockIdx.x, head = blockIdx.y, b = blockIdx.z;
    const int qg0 = qt * 64;

    const float* Qg = q + (size_t)((b * NHEAD + head) * TT + qg0) * HDIM;
    const float* Kg = k + (size_t)(b * NHEAD + head) * TT * HDIM;
    const float* Vg = v + (size_t)(b * NHEAD + head) * TT * HDIM;

    // stage Q into Ks, pull A-fragments (row w*16+gl / +8)
    for (int i = tid; i < 64 * 16; i += 128) {
        int r = i >> 4, c4 = (i & 15) << 2;
        *(float4*)&Ks[r * AST + c4] = *(const float4*)&Qg[r * 64 + c4];
    }
    __syncthreads();
    uint32_t qf[8][4];
    #pragma unroll
    for (int ks = 0; ks < 8; ks++) {
        qf[ks][0] = __float_as_uint(tf32r(Ks[(w*16+gl  ) * AST + ks*8 + cl    ]));
        qf[ks][1] = __float_as_uint(tf32r(Ks[(w*16+gl+8) * AST + ks*8 + cl    ]));
        qf[ks][2] = __float_as_uint(tf32r(Ks[(w*16+gl  ) * AST + ks*8 + cl + 4]));
        qf[ks][3] = __float_as_uint(tf32r(Ks[(w*16+gl+8) * AST + ks*8 + cl + 4]));
    }

    float m0 = -1e30f, m1 = -1e30f, l0 = 0.f, l1 = 0.f;
    float oacc[8][4];
    #pragma unroll
    for (int nt = 0; nt < 8; nt++)
        #pragma unroll
        for (int r = 0; r < 4; r++) oacc[nt][r] = 0.f;

    for (int kt = 0; kt <= qt; kt++) {
        __syncthreads();   // prior iter done reading Ks/Vs
        const float* Kt = Kg + (size_t)kt * 64 * 64;
        const float* Vt = Vg + (size_t)kt * 64 * 64;
        for (int i = tid; i < 64 * 16; i += 128) {
            int r = i >> 4, c4 = (i & 15) << 2;
            float4 kv = *(const float4*)&Kt[r * 64 + c4];
            float4 vv = *(const float4*)&Vt[r * 64 + c4];
            kv.x = tf32r(kv.x); kv.y = tf32r(kv.y);
            kv.z = tf32r(kv.z); kv.w = tf32r(kv.w);
            vv.x = tf32r(vv.x); vv.y = tf32r(vv.y);
            vv.z = tf32r(vv.z); vv.w = tf32r(vv.w);
            *(float4*)&Ks[r * AST + c4] = kv;
            *(float4*)&Vs[r * VST + c4] = vv;
        }
        __syncthreads();

        // S = Q K^T  (M=16 rows of this warp, N=64 keys)
        float sacc[8][4];
        #pragma unroll
        for (int nt = 0; nt < 8; nt++)
            #pragma unroll
            for (int r = 0; r < 4; r++) sacc[nt][r] = 0.f;
        #pragma unroll
        for (int ks = 0; ks < 8; ks++) {
            #pragma unroll
            for (int nt = 0; nt < 8; nt++) {
                uint32_t bf[2];
                bf[0] = __float_as_uint(Ks[(nt*8+gl) * AST + ks*8 + cl    ]);
                bf[1] = __float_as_uint(Ks[(nt*8+gl) * AST + ks*8 + cl + 4]);
                mma8(sacc[nt], qf[ks], bf);
            }
        }
        // scale + diagonal mask
        #pragma unroll
        for (int nt = 0; nt < 8; nt++)
            #pragma unroll
            for (int r = 0; r < 4; r++) sacc[nt][r] *= 0.125f;
        if (kt == qt) {
            #pragma unroll
            for (int nt = 0; nt < 8; nt++)
                #pragma unroll
                for (int j = 0; j < 2; j++) {
                    int key = nt * 8 + 2 * cl + j;
                    if (key > w * 16 + gl)     sacc[nt][j]     = 1e-9f;
                    if (key > w * 16 + gl + 8) sacc[nt][2 + j] = 1e-9f;
                }
        }
        // register softmax (rows gl and gl+8 of this warp's 16)
        float rm0 = -1e30f, rm1 = -1e30f;
        #pragma unroll
        for (int nt = 0; nt < 8; nt++) {
            rm0 = fmaxf(rm0, fmaxf(sacc[nt][0], sacc[nt][1]));
            rm1 = fmaxf(rm1, fmaxf(sacc[nt][2], sacc[nt][3]));
        }
        rm0 = fmaxf(rm0, __shfl_xor_sync(0xffffffffu, rm0, 1));
        rm0 = fmaxf(rm0, __shfl_xor_sync(0xffffffffu, rm0, 2));
        rm1 = fmaxf(rm1, __shfl_xor_sync(0xffffffffu, rm1, 1));
        rm1 = fmaxf(rm1, __shfl_xor_sync(0xffffffffu, rm1, 2));
        float mn0 = fmaxf(m0, rm0), mn1 = fmaxf(m1, rm1);
        float a0 = __expf(m0 - mn0), a1 = __expf(m1 - mn1);
        m0 = mn0; m1 = mn1;
        float rs0 = 0.f, rs1 = 0.f;
        #pragma unroll
        for (int nt = 0; nt < 8; nt++) {
            float p0 = __expf(sacc[nt][0] - mn0);
            float p1 = __expf(sacc[nt][1] - mn0);
            float p2 = __expf(sacc[nt][2] - mn1);
            float p3 = __expf(sacc[nt][3] - mn1);
            rs0 += p0 + p1; rs1 += p2 + p3;
            *(float2*)&Ps[(w*16+gl  ) * AST + nt*8 + 2*cl] =
                make_float2(tf32r(p0), tf32r(p1));
            *(float2*)&Ps[(w*16+gl+8) * AST + nt*8 + 2*cl] =
                make_float2(tf32r(p2), tf32r(p3));
        }
        rs0 += __shfl_xor_sync(0xffffffffu, rs0, 1);
        rs0 += __shfl_xor_sync(0xffffffffu, rs0, 2);
        rs1 += __shfl_xor_sync(0xffffffffu, rs1, 1);
        rs1 += __shfl_xor_sync(0xffffffffu, rs1, 2);
        l0 = l0 * a0 + rs0;
        l1 = l1 * a1 + rs1;
        #pragma unroll
        for (int nt = 0; nt < 8; nt++) {
            oacc[nt][0] *= a0; oacc[nt][1] *= a0;
            oacc[nt][2] *= a1; oacc[nt][3] *= a1;
        }
        __syncwarp();   // P rows are warp-private

        // O += P V  (A = P fragments, B = V fragments)
        #pragma unroll
        for (int ks = 0; ks < 8; ks++) {
            uint32_t af[4];
            af[0] = __float_as_uint(Ps[(w*16+gl  ) * AST + ks*8 + cl    ]);
            af[1] = __float_as_uint(Ps[(w*16+gl+8) * AST + ks*8 + cl    ]);
            af[2] = __float_as_uint(Ps[(w*16+gl  ) * AST + ks*8 + cl + 4]);
            af[3] = __float_as_uint(Ps[(w*16+gl+8) * AST + ks*8 + cl + 4]);
            #pragma unroll
            for (int nt = 0; nt < 8; nt++) {
                uint32_t bf[2];
                bf[0] = __float_as_uint(Vs[(ks*8+cl  ) * VST + nt*8 + gl]);
                bf[1] = __float_as_uint(Vs[(ks*8+cl+4) * VST + nt*8 + gl]);
                mma8(oacc[nt], af, bf);
            }
        }
    }
    __syncthreads();   // all warps done with Ps/Vs

    // ---- virtual masked tile: rows [(qt+1)*64, 1024) all score 1e-9 ----
    if (qt < 15) {
        const int mstart = (qt + 1) * 64;
        const float nmask = (float)(TT - mstart);
        {
            float ps = 0.f;
            const int col = tid & 63, seg = tid >> 6;   // 2 segments
            for (int r = mstart + seg; r < TT; r += 2)
                ps += Vg[(size_t)r * 64 + col];
            Ps[seg * 64 + col] = ps;
        }
        __syncthreads();
        float nn0 = fmaxf(m0, 1e-9f), nn1 = fmaxf(m1, 1e-9f);
        float a0 = __expf(m0 - nn0), a1 = __expf(m1 - nn1);
        float e0 = __expf(1e-9f - nn0), e1 = __expf(1e-9f - nn1);
        l0 = l0 * a0 + nmask * e0;
        l1 = l1 * a1 + nmask * e1;
        #pragma unroll
        for (int nt = 0; nt < 8; nt++) {
            int col = nt * 8 + 2 * cl;
            float vs0 = Ps[col]     + Ps[64 + col];
            float vs1 = Ps[col + 1] + Ps[64 + col + 1];
            oacc[nt][0] = oacc[nt][0] * a0 + e0 * vs0;
            oacc[nt][1] = oacc[nt][1] * a0 + e0 * vs1;
            oacc[nt][2] = oacc[nt][2] * a1 + e1 * vs0;
            oacc[nt][3] = oacc[nt][3] * a1 + e1 * vs1;
        }
    }

    // ---- epilogue: x1 = x + y ----
    const float inv0 = 1.0f / l0, inv1 = 1.0f / l1;
    const size_t base0 = ((size_t)(b * TT + qg0 + w*16 + gl    )) * HH + head * HDIM;
    const size_t base1 = ((size_t)(b * TT + qg0 + w*16 + gl + 8)) * HH + head * HDIM;
    #pragma unroll
    for (int nt = 0; nt < 8; nt++) {
        int col = nt * 8 + 2 * cl;
        float2 xa = *(const float2*)&x[base0 + col];
        float2 xb = *(const float2*)&x[base1 + col];
        *(float2*)&x1[base0 + col] =
            make_float2(xa.x + oacc[nt][0] * inv0, xa.y + oacc[nt][1] * inv0);
        *(float2*)&x1[base1 + col] =
            make_float2(xb.x + oacc[nt][2] * inv1, xb.y + oacc[nt][3] * inv1);
    }
}

// ---------------- launch ----------------
extern "C" void kernel_launch(void* const* d_in, const int* in_sizes, int n_in,
                              void* d_out, int out_size)
{
    (void)in_sizes; (void)n_in; (void)out_size;
    const float* x    = (const float*)d_in[0];
    const float* ln1g = (const float*)d_in[1];
    const float* ln1b = (const float*)d_in[2];
    const float* ln2g = (const float*)d_in[3];
    const float* ln2b = (const float*)d_in[4];
    const float* Wq   = (const float*)d_in[5];
    const float* bq   = (const float*)d_in[6];
    const float* Wk   = (const float*)d_in[7];
    const float* bk   = (const float*)d_in[8];
    const float* Wv   = (const float*)d_in[9];
    const float* bv   = (const float*)d_in[10];
    const float* W1   = (const float*)d_in[11];
    const float* b1   = (const float*)d_in[12];
    const float* W2   = (const float*)d_in[13];
    const float* b2   = (const float*)d_in[14];
    float* out = (float*)d_out;

    float *hp, *q, *k, *v, *x1, *m1, *wqkv, *w1, *w2;
    cudaGetSymbolAddress((void**)&hp,   g_hp);
    cudaGetSymbolAddress((void**)&q,    g_q);
    cudaGetSymbolAddress((void**)&k,    g_k);
    cudaGetSymbolAddress((void**)&v,    g_v);
    cudaGetSymbolAddress((void**)&x1,   g_x1);
    cudaGetSymbolAddress((void**)&m1,   g_m1);
    cudaGetSymbolAddress((void**)&wqkv, g_wqkv);
    cudaGetSymbolAddress((void**)&w1,   g_w1);
    cudaGetSymbolAddress((void**)&w2,   g_w2);

    cudaFuncSetAttribute(attn_tc,
                         cudaFuncAttributeMaxDynamicSharedMemorySize, (int)ATTN_SMEM);
    cudaFuncSetAttribute(gemm_mma<EPI_QKV>,
                         cudaFuncAttributeMaxDynamicSharedMemorySize, GEMM_SMEM);
    cudaFuncSetAttribute(gemm_mma<EPI_GELU>,
                         cudaFuncAttributeMaxDynamicSharedMemorySize, GEMM_SMEM);
    cudaFuncSetAttribute(gemm_mma<EPI_RES>,
                         cudaFuncAttributeMaxDynamicSharedMemorySize, GEMM_SMEM);

    // fused weight prep (all 5 weights, one launch)
    prep_all<<<2816, 256>>>(Wq, Wk, Wv, W1, W2, wqkv, w1, w2);

    // LN1 -> hp (A-fragment order)
    ln_kernel<<<ROWS, 256>>>(x, ln1g, ln1b, hp);
    // fused QKV projection: N=3072, head-permuted stores into q/k/v
    gemm_mma<EPI_QKV><<<dim3(3 * HH / 128, ROWS / 128), 128, GEMM_SMEM>>>(
        hp, wqkv, bq, bk, bv, nullptr, q, k, v, 3 * HH, HH);
    // tensor-core attention + residual
    attn_tc<<<dim3(TT / 64, NHEAD, BB), 128, ATTN_SMEM>>>(q, k, v, x, x1);
    // LN2 -> hp (A-fragment order)
    ln_kernel<<<ROWS, 256>>>(x1, ln2g, ln2b, hp);
    // MLP: W1 gemm writes m1 in A-fragment order; W2 gemm reads it back
    gemm_mma<EPI_GELU><<<dim3(4 * HH / 128, ROWS / 128), 128, GEMM_SMEM>>>(
        hp, w1, b1, nullptr, nullptr, nullptr, m1, nullptr, nullptr, 4 * HH, HH);
    gemm_mma<EPI_RES><<<dim3(HH / 128, ROWS / 128), 128, GEMM_SMEM>>>(
        m1, w2, b2, nullptr, nullptr, x1, out, nullptr, nullptr, HH, 4 * HH);
}